// round 12
// baseline (speedup 1.0000x reference)
#include <cuda_runtime.h>
#include <cstdio>
#include <cstdint>

#define B_ 2
#define T_ 2048
#define C_ 2048
#define H_ 16
#define D_ 128

// ---------------- scratch (device globals: no runtime allocation) ----------------
__device__ float g_qkv[(size_t)B_ * T_ * 3 * C_];
__device__ float g_Q[(size_t)B_ * H_ * T_ * D_];
__device__ float g_K[(size_t)B_ * H_ * T_ * D_];      // PACKED B-frag tiles
__device__ float g_V[(size_t)B_ * H_ * T_ * D_];      // PACKED B-frag tiles
__device__ float g_attn[(size_t)B_ * T_ * C_];        // PACKED-A layout
__device__ float g_xc[(size_t)B_ * T_ * C_];          // packed-A tf32 x
__device__ float g_wqkvC[(size_t)C_ * 3 * C_];        // packed-B tf32 W_qkv
__device__ float g_wprojC[(size_t)C_ * C_];           // packed-B tf32 W_proj

// ---------------- helpers -------------------------------------------------------
__device__ __forceinline__ float to_tf32(float x) {
    unsigned u;
    asm("cvt.rna.tf32.f32 %0, %1;" : "=r"(u) : "f"(x));
    return __uint_as_float(u);
}

__device__ __forceinline__ void mma_tf32(float c[4], const float a[4], const float b[2]) {
    asm volatile(
        "mma.sync.aligned.m16n8k8.row.col.f32.tf32.tf32.f32 "
        "{%0,%1,%2,%3}, {%4,%5,%6,%7}, {%8,%9}, {%0,%1,%2,%3};"
        : "+f"(c[0]), "+f"(c[1]), "+f"(c[2]), "+f"(c[3])
        : "r"(__float_as_uint(a[0])), "r"(__float_as_uint(a[1])),
          "r"(__float_as_uint(a[2])), "r"(__float_as_uint(a[3])),
          "r"(__float_as_uint(b[0])), "r"(__float_as_uint(b[1])));
}

__device__ __forceinline__ uint32_t smem_u32(const void* p) {
    uint32_t a;
    asm("{ .reg .u64 t; cvta.to.shared.u64 t, %1; cvt.u32.u64 %0, t; }" : "=r"(a) : "l"(p));
    return a;
}

#define CP_ASYNC16(dst, src) \
    asm volatile("cp.async.cg.shared.global [%0], [%1], 16;" :: "r"(dst), "l"(src) : "memory")
#define CP_COMMIT() asm volatile("cp.async.commit_group;" ::: "memory")

// ============ GEMM v5b: packed operands, prefetch-before-compute ================
#define V5_BM 128
#define V5_BN 128
#define V5_BK 32
#define V5_ASTR 72
#define V5_BSTR 264
#define V5_AFLOATS (64 * V5_ASTR)             // 4608
#define V5_BFLOATS (16 * V5_BSTR)             // 4224
#define V5_STAGEF (V5_AFLOATS + V5_BFLOATS)   // 8832 floats
#define V5_NST 3
#define V5_SMEM_BYTES (V5_NST * V5_STAGEF * 4)  // 105984

__global__ __launch_bounds__(256, 2) void gemm_v5_kernel(
    const float* __restrict__ Ap, const float* __restrict__ Bp, float* __restrict__ Cm,
    int M, int N, int K)
{
    extern __shared__ float sm[];

    const int tid = threadIdx.x;
    const int warp = tid >> 5;
    const int lane = tid & 31;
    const int lm = lane >> 2;
    const int lk = lane & 3;

    const int m0 = blockIdx.y * V5_BM;
    const int n0 = blockIdx.x * V5_BN;
    const int wm = (warp >> 2) * 64;
    const int wn = (warp & 3) * 32;

    const uint32_t smb = smem_u32(sm);

    float acc[4][4][4];
#pragma unroll
    for (int mi = 0; mi < 4; mi++)
#pragma unroll
        for (int ni = 0; ni < 4; ni++)
#pragma unroll
            for (int r = 0; r < 4; r++) acc[mi][ni][r] = 0.0f;

    auto load_stage = [&](int s) {
        const int k0 = s * V5_BK;
        const uint32_t base = smb + (uint32_t)((s % V5_NST) * V5_STAGEF * 4);
#pragma unroll
        for (int i = 0; i < 4; i++) {
            int id = tid + i * 256;
            int p = id >> 4, kc = id & 15;
            uint32_t dst = base + (uint32_t)((p * V5_ASTR + kc * 4) * 4);
            const float* src = Ap + ((size_t)(m0 / 2 + p) * K + k0 + kc * 2) * 2;
            CP_ASYNC16(dst, src);
        }
        const uint32_t bbase = base + V5_AFLOATS * 4;
#pragma unroll
        for (int i = 0; i < 4; i++) {
            int id = tid + i * 256;
            int kp = id >> 6, nc = id & 63;
            uint32_t dst = bbase + (uint32_t)((kp * V5_BSTR + nc * 4) * 4);
            const float* src = Bp + ((size_t)(k0 / 2 + kp) * N + n0 + nc * 2) * 2;
            CP_ASYNC16(dst, src);
        }
        CP_COMMIT();
    };

    const int nst = K / V5_BK;   // 64
    load_stage(0);
    load_stage(1);

    for (int ks = 0; ks < nst; ks++) {
        asm volatile("cp.async.wait_group %0;" :: "n"(1) : "memory");
        __syncthreads();

        // Prefetch FIRST: slot (ks+2)%3 == (ks-1)%3 was consumed at iter ks-1,
        // protected by the barrier above. Issuing before compute overlaps the
        // LSU/L2 latency under the MMA block. One commit per iter keeps the
        // wait_group(1) arithmetic exact through the tail.
        if (ks + 2 < nst) load_stage(ks + 2);
        else CP_COMMIT();

        const float* As = sm + (size_t)(ks % V5_NST) * V5_STAGEF;
        const float* Bs = As + V5_AFLOATS;

#pragma unroll
        for (int kk = 0; kk < V5_BK; kk += 8) {
            float afr[4][4];
#pragma unroll
            for (int mi = 0; mi < 4; mi++) {
                int aw = (((wm >> 4) + mi) * 8 + lm) * V5_ASTR + (kk + lk) * 2;
                *(float2*)&afr[mi][0] = *(const float2*)&As[aw];
                *(float2*)&afr[mi][2] = *(const float2*)&As[aw + 8];
            }
            float bfr[4][2];
#pragma unroll
            for (int ni = 0; ni < 4; ni++) {
                int bw = ((kk >> 3) * 4 + lk) * V5_BSTR + (wn + ni * 8 + lm) * 2;
                *(float2*)&bfr[ni][0] = *(const float2*)&Bs[bw];
            }
#pragma unroll
            for (int mi = 0; mi < 4; mi++)
#pragma unroll
                for (int ni = 0; ni < 4; ni++)
                    mma_tf32(acc[mi][ni], afr[mi], bfr[ni]);
        }
    }

#pragma unroll
    for (int mi = 0; mi < 4; mi++) {
#pragma unroll
        for (int ni = 0; ni < 4; ni++) {
            int gr = m0 + wm + mi * 16 + lm;
            int gc = n0 + wn + ni * 8 + lk * 2;
            float* p0 = Cm + (size_t)gr * N + gc;
            float* p1 = Cm + (size_t)(gr + 8) * N + gc;
            *(float2*)p0 = make_float2(acc[mi][ni][0], acc[mi][ni][1]);
            *(float2*)p1 = make_float2(acc[mi][ni][2], acc[mi][ni][3]);
        }
    }
}

// ---------------- pack pre-passes (tf32-round + layout) -------------------------
__global__ __launch_bounds__(256) void pack_a_kernel(
    const float* __restrict__ src, float* __restrict__ dst, int K, int nchunk)
{
    int c = blockIdx.x * blockDim.x + threadIdx.x;
    if (c >= nchunk) return;
    int kh = K >> 1;
    int p = c / kh, kc = c - p * kh;
    int m = (p >> 3) * 16 + (p & 7);
    int k = kc * 2;
    const float* r0 = src + (size_t)m * K + k;
    const float* r1 = r0 + (size_t)8 * K;
    float4 v;
    v.x = to_tf32(r0[0]); v.y = to_tf32(r1[0]);
    v.z = to_tf32(r0[1]); v.w = to_tf32(r1[1]);
    *(float4*)(dst + (size_t)c * 4) = v;
}

__global__ __launch_bounds__(256) void pack_b_kernel(
    const float* __restrict__ src, float* __restrict__ dst, int N, int nchunk)
{
    int c = blockIdx.x * blockDim.x + threadIdx.x;
    if (c >= nchunk) return;
    int nh = N >> 1;
    int kp = c / nh, nc = c - kp * nh;
    int k = (kp >> 2) * 8 + (kp & 3);
    int n = nc * 2;
    const float* r0 = src + (size_t)k * N + n;
    const float* r1 = r0 + (size_t)4 * N;
    float4 v;
    v.x = to_tf32(r0[0]); v.y = to_tf32(r1[0]);
    v.z = to_tf32(r0[1]); v.w = to_tf32(r1[1]);
    *(float4*)(dst + (size_t)c * 4) = v;
}

// ---------------- RoPE + pack K/V into B-fragment tile images -------------------
__global__ __launch_bounds__(256) void rope_pack_kernel(
    const float* __restrict__ qkv, const float* __restrict__ cosg,
    const float* __restrict__ sing,
    float* __restrict__ Q, float* __restrict__ Kp, float* __restrict__ Vp)
{
    __shared__ float stK[4096];
    __shared__ float stV[4096];
    const int kt = blockIdx.x;       // 0..63
    const int h = blockIdx.y;
    const int b = blockIdx.z;
    const int tid = threadIdx.x;
    const int t0 = kt * 32;
    const size_t bh = (size_t)(b * H_ + h);

#pragma unroll
    for (int i = 0; i < 8; i++) {
        int idx = tid + i * 256;
        int r = idx >> 6, d = idx & 63;
        int t = t0 + r;
        const float* base = qkv + ((size_t)(b * T_ + t)) * (3 * C_) + h * D_;
        float c = cosg[t * 64 + d];
        float s = sing[t * 64 + d];
        float q1 = base[d], q2 = base[d + 64];
        float* Qrow = Q + (bh * T_ + t) * D_;
        Qrow[d]      = q1 * c - q2 * s;
        Qrow[d + 64] = q1 * s + q2 * c;
        float k1 = base[C_ + d], k2 = base[C_ + d + 64];
        float kr1 = to_tf32(k1 * c - k2 * s);
        float kr2 = to_tf32(k1 * s + k2 * c);
        stK[((r >> 3) * 16 + (d >> 3)) * 64 + ((r & 7) * 4 + (d & 3)) * 2 + ((d >> 2) & 1)] = kr1;
        int d2 = d + 64;
        stK[((r >> 3) * 16 + (d2 >> 3)) * 64 + ((r & 7) * 4 + (d2 & 3)) * 2 + ((d2 >> 2) & 1)] = kr2;
    }
#pragma unroll
    for (int i = 0; i < 16; i++) {
        int idx = tid + i * 256;
        int r = idx >> 7, d = idx & 127;
        int t = t0 + r;
        const float* base = qkv + ((size_t)(b * T_ + t)) * (3 * C_) + h * D_;
        float v = to_tf32(base[2 * C_ + d]);
        stV[((r >> 3) * 16 + (d >> 3)) * 64 + ((d & 7) * 4 + (r & 3)) * 2 + ((r >> 2) & 1)] = v;
    }
    __syncthreads();
    float* kout = Kp + bh * ((size_t)T_ * D_) + (size_t)kt * 4096;
    float* vout = Vp + bh * ((size_t)T_ * D_) + (size_t)kt * 4096;
#pragma unroll
    for (int i = 0; i < 4; i++) {
        int c = tid + i * 256;
        *(float4*)(kout + c * 4) = *(const float4*)(stK + c * 4);
        *(float4*)(vout + c * 4) = *(const float4*)(stV + c * 4);
    }
}

// ---------------- attention v3b: LPT order, Q in regs, cp.async packed K/V ------
#define KV_TILE_F (64 * 68)
#define PS_FLOATS (16 * 132)
#define ATTN_SMEM_FLOATS (2 * 2 * KV_TILE_F + PS_FLOATS)   // 78080 B

__global__ __launch_bounds__(128, 2) void attn_mma_kernel(
    const float* __restrict__ Q, const float* __restrict__ Kp,
    const float* __restrict__ Vp)
{
    extern __shared__ float sm[];
    float* Ps = sm + 2 * 2 * KV_TILE_F;

    // LPT: largest-work q-blocks first (work ∝ qb+1)
    const int qb = (int)gridDim.x - 1 - (int)blockIdx.x;
    const int bh = blockIdx.y;
    const int b = bh >> 4;
    const int h = bh & 15;
    const int tid = threadIdx.x;
    const int w = tid >> 5;
    const int lane = tid & 31;
    const int lm = lane >> 2;
    const int lk = lane & 3;
    const int q0 = qb * 64;

    const float* Qg = Q + ((size_t)bh * T_ + q0) * D_;
    const float* Kg = Kp + (size_t)bh * T_ * D_;
    const float* Vg = Vp + (size_t)bh * T_ * D_;
    const uint32_t smb = smem_u32(sm);

    const int row0g = q0 + w * 16 + lm;
    const int row1g = row0g + 8;

    float qfr[16][4];
    {
        const float* q0p = Qg + (size_t)(w * 16 + lm) * D_;
        const float* q1p = q0p + 8 * D_;
#pragma unroll
        for (int dk = 0; dk < 16; dk++) {
            int col = dk * 8 + lk;
            qfr[dk][0] = to_tf32(q0p[col]);
            qfr[dk][1] = to_tf32(q1p[col]);
            qfr[dk][2] = to_tf32(q0p[col + 4]);
            qfr[dk][3] = to_tf32(q1p[col + 4]);
        }
    }

    float m0 = -1e30f, m1 = -1e30f, l0 = 0.0f, l1 = 0.0f;
    float oacc[16][4];
#pragma unroll
    for (int ni = 0; ni < 16; ni++)
#pragma unroll
        for (int r = 0; r < 4; r++) oacc[ni][r] = 0.0f;

    const float scale = 0.08838834764831845f;
    const int nkv = (q0 + 64) / 32;

    auto load_kv = [&](int kt) {
        const uint32_t dstb = smb + (uint32_t)((kt & 1) * 2 * KV_TILE_F * 4);
        const float* ksrc = Kg + (size_t)kt * 4096;
        const float* vsrc = Vg + (size_t)kt * 4096;
#pragma unroll
        for (int i = 0; i < 8; i++) {
            int c = tid + i * 128;
            int sub = c >> 4, q = c & 15;
            uint32_t off = (uint32_t)((sub * 68 + q * 4) * 4);
            CP_ASYNC16(dstb + off, ksrc + c * 4);
            CP_ASYNC16(dstb + KV_TILE_F * 4 + off, vsrc + c * 4);
        }
        CP_COMMIT();
    };

    load_kv(0);

    for (int kt = 0; kt < nkv; kt++) {
        const int kv0 = kt * 32;
        asm volatile("cp.async.wait_group 0;" ::: "memory");
        __syncthreads();
        if (kt + 1 < nkv) load_kv(kt + 1);

        const float* Ks = sm + (kt & 1) * 2 * KV_TILE_F;
        const float* Vs = Ks + KV_TILE_F;

        float sacc[4][4];
#pragma unroll
        for (int ni = 0; ni < 4; ni++)
#pragma unroll
            for (int r = 0; r < 4; r++) sacc[ni][r] = 0.0f;

#pragma unroll
        for (int dk = 0; dk < 16; dk++) {
#pragma unroll
            for (int ni = 0; ni < 4; ni++) {
                float bfr[2];
                *(float2*)bfr = *(float2*)&Ks[(ni * 16 + dk) * 68 + lane * 2];
                mma_tf32(sacc[ni], qfr[dk], bfr);
            }
        }

        const bool needMask = (kt >= 2 * qb);
#pragma unroll
        for (int ni = 0; ni < 4; ni++) {
            int c0 = kv0 + ni * 8 + 2 * lk;
#pragma unroll
            for (int r = 0; r < 4; r++) sacc[ni][r] *= scale;
            if (needMask) {
                if (c0     > row0g) sacc[ni][0] = -1e30f;
                if (c0 + 1 > row0g) sacc[ni][1] = -1e30f;
                if (c0     > row1g) sacc[ni][2] = -1e30f;
                if (c0 + 1 > row1g) sacc[ni][3] = -1e30f;
            }
        }

        float rmax0 = -1e30f, rmax1 = -1e30f;
#pragma unroll
        for (int ni = 0; ni < 4; ni++) {
            rmax0 = fmaxf(rmax0, fmaxf(sacc[ni][0], sacc[ni][1]));
            rmax1 = fmaxf(rmax1, fmaxf(sacc[ni][2], sacc[ni][3]));
        }
        rmax0 = fmaxf(rmax0, __shfl_xor_sync(0xffffffffu, rmax0, 1));
        rmax0 = fmaxf(rmax0, __shfl_xor_sync(0xffffffffu, rmax0, 2));
        rmax1 = fmaxf(rmax1, __shfl_xor_sync(0xffffffffu, rmax1, 1));
        rmax1 = fmaxf(rmax1, __shfl_xor_sync(0xffffffffu, rmax1, 2));
        float mn0 = fmaxf(m0, rmax0);
        float mn1 = fmaxf(m1, rmax1);
        float al0 = __expf(m0 - mn0);
        float al1 = __expf(m1 - mn1);
        float rs0 = 0.0f, rs1 = 0.0f;
#pragma unroll
        for (int ni = 0; ni < 4; ni++) {
            sacc[ni][0] = __expf(sacc[ni][0] - mn0);
            sacc[ni][1] = __expf(sacc[ni][1] - mn0);
            sacc[ni][2] = __expf(sacc[ni][2] - mn1);
            sacc[ni][3] = __expf(sacc[ni][3] - mn1);
            rs0 += sacc[ni][0] + sacc[ni][1];
            rs1 += sacc[ni][2] + sacc[ni][3];
        }
        rs0 += __shfl_xor_sync(0xffffffffu, rs0, 1);
        rs0 += __shfl_xor_sync(0xffffffffu, rs0, 2);
        rs1 += __shfl_xor_sync(0xffffffffu, rs1, 1);
        rs1 += __shfl_xor_sync(0xffffffffu, rs1, 2);
        l0 = l0 * al0 + rs0;
        l1 = l1 * al1 + rs1;
        m0 = mn0;
        m1 = mn1;
#pragma unroll
        for (int ni = 0; ni < 16; ni++) {
            oacc[ni][0] *= al0; oacc[ni][1] *= al0;
            oacc[ni][2] *= al1; oacc[ni][3] *= al1;
        }

#pragma unroll
        for (int ni = 0; ni < 4; ni++) {
            float* tp = &Ps[(w * 4 + ni) * 132];
            int c0 = 2 * lk;
            int lf0 = (lm << 2) | (c0 & 3);
            int rh0 = (c0 >= 4) ? 2 : 0;
            tp[lf0 * 4 + rh0]     = to_tf32(sacc[ni][0]);
            tp[lf0 * 4 + rh0 + 1] = to_tf32(sacc[ni][2]);
            int c1 = 2 * lk + 1;
            int lf1 = (lm << 2) | (c1 & 3);
            int rh1 = (c1 >= 4) ? 2 : 0;
            tp[lf1 * 4 + rh1]     = to_tf32(sacc[ni][1]);
            tp[lf1 * 4 + rh1 + 1] = to_tf32(sacc[ni][3]);
        }
        __syncwarp();

#pragma unroll
        for (int kt2 = 0; kt2 < 4; kt2++) {
            float afr[4];
            *(float4*)afr = *(float4*)&Ps[(w * 4 + kt2) * 132 + lane * 4];
#pragma unroll
            for (int ni = 0; ni < 16; ni++) {
                float bfr[2];
                *(float2*)bfr = *(float2*)&Vs[(kt2 * 16 + ni) * 68 + lane * 2];
                mma_tf32(oacc[ni], afr, bfr);
            }
        }
    }

    float inv0 = 1.0f / l0;
    float inv1 = 1.0f / l1;
    const size_t rowg = (size_t)b * T_ + (size_t)row0g;
    const size_t pglob = (rowg >> 4) * 8 + (rowg & 7);
#pragma unroll
    for (int ni = 0; ni < 16; ni++) {
        int col = h * D_ + ni * 8 + 2 * lk;
        float4 v;
        v.x = to_tf32(oacc[ni][0] * inv0);
        v.y = to_tf32(oacc[ni][2] * inv1);
        v.z = to_tf32(oacc[ni][1] * inv0);
        v.w = to_tf32(oacc[ni][3] * inv1);
        *(float4*)&g_attn[(pglob * C_ + col) * 2] = v;
    }
}

// ---------------- launch -------------------------------------------------------
extern "C" void kernel_launch(void* const* d_in, const int* in_sizes, int n_in,
                              void* d_out, int out_size)
{
    const float* x      = (const float*)d_in[0];
    const float* cosg   = (const float*)d_in[1];
    const float* sing   = (const float*)d_in[2];
    const float* W_qkv  = (const float*)d_in[3];
    const float* W_proj = (const float*)d_in[4];
    float* out = (float*)d_out;

    float* qkv;    cudaGetSymbolAddress((void**)&qkv,    g_qkv);
    float* Qb;     cudaGetSymbolAddress((void**)&Qb,     g_Q);
    float* Kb;     cudaGetSymbolAddress((void**)&Kb,     g_K);
    float* Vb;     cudaGetSymbolAddress((void**)&Vb,     g_V);
    float* attn;   cudaGetSymbolAddress((void**)&attn,   g_attn);
    float* xc;     cudaGetSymbolAddress((void**)&xc,     g_xc);
    float* wqkvC;  cudaGetSymbolAddress((void**)&wqkvC,  g_wqkvC);
    float* wprojC; cudaGetSymbolAddress((void**)&wprojC, g_wprojC);

    const int M = B_ * T_;   // 4096

    cudaFuncSetAttribute(gemm_v5_kernel,
                         cudaFuncAttributeMaxDynamicSharedMemorySize, V5_SMEM_BYTES);
    cudaFuncSetAttribute(attn_mma_kernel,
                         cudaFuncAttributeMaxDynamicSharedMemorySize,
                         ATTN_SMEM_FLOATS * sizeof(float));

    // 0) pack + tf32-round operands
    {
        int na = (M * C_) / 4;
        pack_a_kernel<<<(na + 255) / 256, 256>>>(x, xc, C_, na);
        int nbq = (C_ * 3 * C_) / 4;
        pack_b_kernel<<<(nbq + 255) / 256, 256>>>(W_qkv, wqkvC, 3 * C_, nbq);
        int nbp = (C_ * C_) / 4;
        pack_b_kernel<<<(nbp + 255) / 256, 256>>>(W_proj, wprojC, C_, nbp);
    }

    // 1) qkv = x @ W_qkv
    {
        dim3 grid(3 * C_ / V5_BN, M / V5_BM);   // (48, 32)
        gemm_v5_kernel<<<grid, 256, V5_SMEM_BYTES>>>(xc, wqkvC, qkv, M, 3 * C_, C_);
    }
    // 2) RoPE + pack K/V tiles
    {
        dim3 grid(T_ / 32, H_, B_);             // (64, 16, 2)
        rope_pack_kernel<<<grid, 256>>>(qkv, cosg, sing, Qb, Kb, Vb);
    }
    // 3) attention -> g_attn (packed-A), LPT order
    {
        dim3 grid(T_ / 64, B_ * H_);            // (32, 32)
        attn_mma_kernel<<<grid, 128, ATTN_SMEM_FLOATS * sizeof(float)>>>(Qb, Kb, Vb);
    }
    // 4) out = attn @ W_proj
    {
        dim3 grid(C_ / V5_BN, M / V5_BM);       // (16, 32)
        gemm_v5_kernel<<<grid, 256, V5_SMEM_BYTES>>>(attn, wprojC, out, M, C_, C_);
    }
}

// round 13
// speedup vs baseline: 1.0206x; 1.0206x over previous
#include <cuda_runtime.h>
#include <cstdio>
#include <cstdint>

#define B_ 2
#define T_ 2048
#define C_ 2048
#define H_ 16
#define D_ 128

// ---------------- scratch (device globals: no runtime allocation) ----------------
__device__ float g_qkv[(size_t)B_ * T_ * 3 * C_];
__device__ float g_Q[(size_t)B_ * H_ * T_ * D_];
__device__ float g_K[(size_t)B_ * H_ * T_ * D_];      // PACKED B-frag tiles
__device__ float g_V[(size_t)B_ * H_ * T_ * D_];      // PACKED B-frag tiles
__device__ float g_attn[(size_t)B_ * T_ * C_];        // PACKED-A layout
__device__ float g_xc[(size_t)B_ * T_ * C_];          // packed-A tf32 x
__device__ float g_wqkvC[(size_t)C_ * 3 * C_];        // packed-B tf32 W_qkv
__device__ float g_wprojC[(size_t)C_ * C_];           // packed-B tf32 W_proj

// ---------------- helpers -------------------------------------------------------
__device__ __forceinline__ float to_tf32(float x) {
    unsigned u;
    asm("cvt.rna.tf32.f32 %0, %1;" : "=r"(u) : "f"(x));
    return __uint_as_float(u);
}

__device__ __forceinline__ void mma_tf32(float c[4], const float a[4], const float b[2]) {
    asm volatile(
        "mma.sync.aligned.m16n8k8.row.col.f32.tf32.tf32.f32 "
        "{%0,%1,%2,%3}, {%4,%5,%6,%7}, {%8,%9}, {%0,%1,%2,%3};"
        : "+f"(c[0]), "+f"(c[1]), "+f"(c[2]), "+f"(c[3])
        : "r"(__float_as_uint(a[0])), "r"(__float_as_uint(a[1])),
          "r"(__float_as_uint(a[2])), "r"(__float_as_uint(a[3])),
          "r"(__float_as_uint(b[0])), "r"(__float_as_uint(b[1])));
}

__device__ __forceinline__ uint32_t smem_u32(const void* p) {
    uint32_t a;
    asm("{ .reg .u64 t; cvta.to.shared.u64 t, %1; cvt.u32.u64 %0, t; }" : "=r"(a) : "l"(p));
    return a;
}

#define CP_ASYNC16(dst, src) \
    asm volatile("cp.async.cg.shared.global [%0], [%1], 16;" :: "r"(dst), "l"(src) : "memory")
#define CP_COMMIT() asm volatile("cp.async.commit_group;" ::: "memory")

// ============ GEMM v5 (R11 ordering): packed operands, prefetch AFTER compute ===
#define V5_BM 128
#define V5_BN 128
#define V5_BK 32
#define V5_ASTR 72
#define V5_BSTR 264
#define V5_AFLOATS (64 * V5_ASTR)             // 4608
#define V5_BFLOATS (16 * V5_BSTR)             // 4224
#define V5_STAGEF (V5_AFLOATS + V5_BFLOATS)   // 8832 floats
#define V5_NST 3
#define V5_SMEM_BYTES (V5_NST * V5_STAGEF * 4)  // 105984

__global__ __launch_bounds__(256, 2) void gemm_v5_kernel(
    const float* __restrict__ Ap, const float* __restrict__ Bp, float* __restrict__ Cm,
    int M, int N, int K)
{
    extern __shared__ float sm[];

    const int tid = threadIdx.x;
    const int warp = tid >> 5;
    const int lane = tid & 31;
    const int lm = lane >> 2;
    const int lk = lane & 3;

    const int m0 = blockIdx.y * V5_BM;
    const int n0 = blockIdx.x * V5_BN;
    const int wm = (warp >> 2) * 64;
    const int wn = (warp & 3) * 32;

    const uint32_t smb = smem_u32(sm);

    float acc[4][4][4];
#pragma unroll
    for (int mi = 0; mi < 4; mi++)
#pragma unroll
        for (int ni = 0; ni < 4; ni++)
#pragma unroll
            for (int r = 0; r < 4; r++) acc[mi][ni][r] = 0.0f;

    auto load_stage = [&](int s) {
        const int k0 = s * V5_BK;
        const uint32_t base = smb + (uint32_t)((s % V5_NST) * V5_STAGEF * 4);
#pragma unroll
        for (int i = 0; i < 4; i++) {
            int id = tid + i * 256;
            int p = id >> 4, kc = id & 15;
            uint32_t dst = base + (uint32_t)((p * V5_ASTR + kc * 4) * 4);
            const float* src = Ap + ((size_t)(m0 / 2 + p) * K + k0 + kc * 2) * 2;
            CP_ASYNC16(dst, src);
        }
        const uint32_t bbase = base + V5_AFLOATS * 4;
#pragma unroll
        for (int i = 0; i < 4; i++) {
            int id = tid + i * 256;
            int kp = id >> 6, nc = id & 63;
            uint32_t dst = bbase + (uint32_t)((kp * V5_BSTR + nc * 4) * 4);
            const float* src = Bp + ((size_t)(k0 / 2 + kp) * N + n0 + nc * 2) * 2;
            CP_ASYNC16(dst, src);
        }
        CP_COMMIT();
    };

    const int nst = K / V5_BK;   // 64
    load_stage(0);
    load_stage(1);

    for (int ks = 0; ks < nst; ks++) {
        asm volatile("cp.async.wait_group %0;" :: "n"(1) : "memory");
        __syncthreads();

        const float* As = sm + (size_t)(ks % V5_NST) * V5_STAGEF;
        const float* Bs = As + V5_AFLOATS;

#pragma unroll
        for (int kk = 0; kk < V5_BK; kk += 8) {
            float afr[4][4];
#pragma unroll
            for (int mi = 0; mi < 4; mi++) {
                int aw = (((wm >> 4) + mi) * 8 + lm) * V5_ASTR + (kk + lk) * 2;
                *(float2*)&afr[mi][0] = *(const float2*)&As[aw];
                *(float2*)&afr[mi][2] = *(const float2*)&As[aw + 8];
            }
            float bfr[4][2];
#pragma unroll
            for (int ni = 0; ni < 4; ni++) {
                int bw = ((kk >> 3) * 4 + lk) * V5_BSTR + (wn + ni * 8 + lm) * 2;
                *(float2*)&bfr[ni][0] = *(const float2*)&Bs[bw];
            }
#pragma unroll
            for (int mi = 0; mi < 4; mi++)
#pragma unroll
                for (int ni = 0; ni < 4; ni++)
                    mma_tf32(acc[mi][ni], afr[mi], bfr[ni]);
        }

        // prefetch AFTER compute (R11 ordering — measured faster than before-compute)
        if (ks + 2 < nst) load_stage(ks + 2);
        else CP_COMMIT();
    }

#pragma unroll
    for (int mi = 0; mi < 4; mi++) {
#pragma unroll
        for (int ni = 0; ni < 4; ni++) {
            int gr = m0 + wm + mi * 16 + lm;
            int gc = n0 + wn + ni * 8 + lk * 2;
            float* p0 = Cm + (size_t)gr * N + gc;
            float* p1 = Cm + (size_t)(gr + 8) * N + gc;
            *(float2*)p0 = make_float2(acc[mi][ni][0], acc[mi][ni][1]);
            *(float2*)p1 = make_float2(acc[mi][ni][2], acc[mi][ni][3]);
        }
    }
}

// ---------------- pack pre-passes (tf32-round + layout) -------------------------
__global__ __launch_bounds__(256) void pack_a_kernel(
    const float* __restrict__ src, float* __restrict__ dst, int K, int nchunk)
{
    int c = blockIdx.x * blockDim.x + threadIdx.x;
    if (c >= nchunk) return;
    int kh = K >> 1;
    int p = c / kh, kc = c - p * kh;
    int m = (p >> 3) * 16 + (p & 7);
    int k = kc * 2;
    const float* r0 = src + (size_t)m * K + k;
    const float* r1 = r0 + (size_t)8 * K;
    float4 v;
    v.x = to_tf32(r0[0]); v.y = to_tf32(r1[0]);
    v.z = to_tf32(r0[1]); v.w = to_tf32(r1[1]);
    *(float4*)(dst + (size_t)c * 4) = v;
}

__global__ __launch_bounds__(256) void pack_b_kernel(
    const float* __restrict__ src, float* __restrict__ dst, int N, int nchunk)
{
    int c = blockIdx.x * blockDim.x + threadIdx.x;
    if (c >= nchunk) return;
    int nh = N >> 1;
    int kp = c / nh, nc = c - kp * nh;
    int k = (kp >> 2) * 8 + (kp & 3);
    int n = nc * 2;
    const float* r0 = src + (size_t)k * N + n;
    const float* r1 = r0 + (size_t)4 * N;
    float4 v;
    v.x = to_tf32(r0[0]); v.y = to_tf32(r1[0]);
    v.z = to_tf32(r0[1]); v.w = to_tf32(r1[1]);
    *(float4*)(dst + (size_t)c * 4) = v;
}

// ---------------- RoPE + pack K/V into B-fragment tile images -------------------
__global__ __launch_bounds__(256) void rope_pack_kernel(
    const float* __restrict__ qkv, const float* __restrict__ cosg,
    const float* __restrict__ sing,
    float* __restrict__ Q, float* __restrict__ Kp, float* __restrict__ Vp)
{
    __shared__ float stK[4096];
    __shared__ float stV[4096];
    const int kt = blockIdx.x;       // 0..63
    const int h = blockIdx.y;
    const int b = blockIdx.z;
    const int tid = threadIdx.x;
    const int t0 = kt * 32;
    const size_t bh = (size_t)(b * H_ + h);

#pragma unroll
    for (int i = 0; i < 8; i++) {
        int idx = tid + i * 256;
        int r = idx >> 6, d = idx & 63;
        int t = t0 + r;
        const float* base = qkv + ((size_t)(b * T_ + t)) * (3 * C_) + h * D_;
        float c = cosg[t * 64 + d];
        float s = sing[t * 64 + d];
        float q1 = base[d], q2 = base[d + 64];
        float* Qrow = Q + (bh * T_ + t) * D_;
        Qrow[d]      = q1 * c - q2 * s;
        Qrow[d + 64] = q1 * s + q2 * c;
        float k1 = base[C_ + d], k2 = base[C_ + d + 64];
        float kr1 = to_tf32(k1 * c - k2 * s);
        float kr2 = to_tf32(k1 * s + k2 * c);
        stK[((r >> 3) * 16 + (d >> 3)) * 64 + ((r & 7) * 4 + (d & 3)) * 2 + ((d >> 2) & 1)] = kr1;
        int d2 = d + 64;
        stK[((r >> 3) * 16 + (d2 >> 3)) * 64 + ((r & 7) * 4 + (d2 & 3)) * 2 + ((d2 >> 2) & 1)] = kr2;
    }
#pragma unroll
    for (int i = 0; i < 16; i++) {
        int idx = tid + i * 256;
        int r = idx >> 7, d = idx & 127;
        int t = t0 + r;
        const float* base = qkv + ((size_t)(b * T_ + t)) * (3 * C_) + h * D_;
        float v = to_tf32(base[2 * C_ + d]);
        stV[((r >> 3) * 16 + (d >> 3)) * 64 + ((d & 7) * 4 + (r & 3)) * 2 + ((r >> 2) & 1)] = v;
    }
    __syncthreads();
    float* kout = Kp + bh * ((size_t)T_ * D_) + (size_t)kt * 4096;
    float* vout = Vp + bh * ((size_t)T_ * D_) + (size_t)kt * 4096;
#pragma unroll
    for (int i = 0; i < 4; i++) {
        int c = tid + i * 256;
        *(float4*)(kout + c * 4) = *(const float4*)(stK + c * 4);
        *(float4*)(vout + c * 4) = *(const float4*)(stV + c * 4);
    }
}

// ---------------- attention v3b: LPT order, Q in regs, cp.async packed K/V ------
#define KV_TILE_F (64 * 68)
#define PS_FLOATS (16 * 132)
#define ATTN_SMEM_FLOATS (2 * 2 * KV_TILE_F + PS_FLOATS)   // 78080 B

__global__ __launch_bounds__(128, 2) void attn_mma_kernel(
    const float* __restrict__ Q, const float* __restrict__ Kp,
    const float* __restrict__ Vp)
{
    extern __shared__ float sm[];
    float* Ps = sm + 2 * 2 * KV_TILE_F;

    // LPT: largest-work q-blocks first (work ∝ qb+1)
    const int qb = (int)gridDim.x - 1 - (int)blockIdx.x;
    const int bh = blockIdx.y;
    const int b = bh >> 4;
    const int h = bh & 15;
    const int tid = threadIdx.x;
    const int w = tid >> 5;
    const int lane = tid & 31;
    const int lm = lane >> 2;
    const int lk = lane & 3;
    const int q0 = qb * 64;

    const float* Qg = Q + ((size_t)bh * T_ + q0) * D_;
    const float* Kg = Kp + (size_t)bh * T_ * D_;
    const float* Vg = Vp + (size_t)bh * T_ * D_;
    const uint32_t smb = smem_u32(sm);

    const int row0g = q0 + w * 16 + lm;
    const int row1g = row0g + 8;

    float qfr[16][4];
    {
        const float* q0p = Qg + (size_t)(w * 16 + lm) * D_;
        const float* q1p = q0p + 8 * D_;
#pragma unroll
        for (int dk = 0; dk < 16; dk++) {
            int col = dk * 8 + lk;
            qfr[dk][0] = to_tf32(q0p[col]);
            qfr[dk][1] = to_tf32(q1p[col]);
            qfr[dk][2] = to_tf32(q0p[col + 4]);
            qfr[dk][3] = to_tf32(q1p[col + 4]);
        }
    }

    float m0 = -1e30f, m1 = -1e30f, l0 = 0.0f, l1 = 0.0f;
    float oacc[16][4];
#pragma unroll
    for (int ni = 0; ni < 16; ni++)
#pragma unroll
        for (int r = 0; r < 4; r++) oacc[ni][r] = 0.0f;

    const float scale = 0.08838834764831845f;
    const int nkv = (q0 + 64) / 32;

    auto load_kv = [&](int kt) {
        const uint32_t dstb = smb + (uint32_t)((kt & 1) * 2 * KV_TILE_F * 4);
        const float* ksrc = Kg + (size_t)kt * 4096;
        const float* vsrc = Vg + (size_t)kt * 4096;
#pragma unroll
        for (int i = 0; i < 8; i++) {
            int c = tid + i * 128;
            int sub = c >> 4, q = c & 15;
            uint32_t off = (uint32_t)((sub * 68 + q * 4) * 4);
            CP_ASYNC16(dstb + off, ksrc + c * 4);
            CP_ASYNC16(dstb + KV_TILE_F * 4 + off, vsrc + c * 4);
        }
        CP_COMMIT();
    };

    load_kv(0);

    for (int kt = 0; kt < nkv; kt++) {
        const int kv0 = kt * 32;
        asm volatile("cp.async.wait_group 0;" ::: "memory");
        __syncthreads();
        if (kt + 1 < nkv) load_kv(kt + 1);

        const float* Ks = sm + (kt & 1) * 2 * KV_TILE_F;
        const float* Vs = Ks + KV_TILE_F;

        float sacc[4][4];
#pragma unroll
        for (int ni = 0; ni < 4; ni++)
#pragma unroll
            for (int r = 0; r < 4; r++) sacc[ni][r] = 0.0f;

#pragma unroll
        for (int dk = 0; dk < 16; dk++) {
#pragma unroll
            for (int ni = 0; ni < 4; ni++) {
                float bfr[2];
                *(float2*)bfr = *(float2*)&Ks[(ni * 16 + dk) * 68 + lane * 2];
                mma_tf32(sacc[ni], qfr[dk], bfr);
            }
        }

        const bool needMask = (kt >= 2 * qb);
#pragma unroll
        for (int ni = 0; ni < 4; ni++) {
            int c0 = kv0 + ni * 8 + 2 * lk;
#pragma unroll
            for (int r = 0; r < 4; r++) sacc[ni][r] *= scale;
            if (needMask) {
                if (c0     > row0g) sacc[ni][0] = -1e30f;
                if (c0 + 1 > row0g) sacc[ni][1] = -1e30f;
                if (c0     > row1g) sacc[ni][2] = -1e30f;
                if (c0 + 1 > row1g) sacc[ni][3] = -1e30f;
            }
        }

        float rmax0 = -1e30f, rmax1 = -1e30f;
#pragma unroll
        for (int ni = 0; ni < 4; ni++) {
            rmax0 = fmaxf(rmax0, fmaxf(sacc[ni][0], sacc[ni][1]));
            rmax1 = fmaxf(rmax1, fmaxf(sacc[ni][2], sacc[ni][3]));
        }
        rmax0 = fmaxf(rmax0, __shfl_xor_sync(0xffffffffu, rmax0, 1));
        rmax0 = fmaxf(rmax0, __shfl_xor_sync(0xffffffffu, rmax0, 2));
        rmax1 = fmaxf(rmax1, __shfl_xor_sync(0xffffffffu, rmax1, 1));
        rmax1 = fmaxf(rmax1, __shfl_xor_sync(0xffffffffu, rmax1, 2));
        float mn0 = fmaxf(m0, rmax0);
        float mn1 = fmaxf(m1, rmax1);
        float al0 = __expf(m0 - mn0);
        float al1 = __expf(m1 - mn1);
        float rs0 = 0.0f, rs1 = 0.0f;
#pragma unroll
        for (int ni = 0; ni < 4; ni++) {
            sacc[ni][0] = __expf(sacc[ni][0] - mn0);
            sacc[ni][1] = __expf(sacc[ni][1] - mn0);
            sacc[ni][2] = __expf(sacc[ni][2] - mn1);
            sacc[ni][3] = __expf(sacc[ni][3] - mn1);
            rs0 += sacc[ni][0] + sacc[ni][1];
            rs1 += sacc[ni][2] + sacc[ni][3];
        }
        rs0 += __shfl_xor_sync(0xffffffffu, rs0, 1);
        rs0 += __shfl_xor_sync(0xffffffffu, rs0, 2);
        rs1 += __shfl_xor_sync(0xffffffffu, rs1, 1);
        rs1 += __shfl_xor_sync(0xffffffffu, rs1, 2);
        l0 = l0 * al0 + rs0;
        l1 = l1 * al1 + rs1;
        m0 = mn0;
        m1 = mn1;
#pragma unroll
        for (int ni = 0; ni < 16; ni++) {
            oacc[ni][0] *= al0; oacc[ni][1] *= al0;
            oacc[ni][2] *= al1; oacc[ni][3] *= al1;
        }

#pragma unroll
        for (int ni = 0; ni < 4; ni++) {
            float* tp = &Ps[(w * 4 + ni) * 132];
            int c0 = 2 * lk;
            int lf0 = (lm << 2) | (c0 & 3);
            int rh0 = (c0 >= 4) ? 2 : 0;
            tp[lf0 * 4 + rh0]     = to_tf32(sacc[ni][0]);
            tp[lf0 * 4 + rh0 + 1] = to_tf32(sacc[ni][2]);
            int c1 = 2 * lk + 1;
            int lf1 = (lm << 2) | (c1 & 3);
            int rh1 = (c1 >= 4) ? 2 : 0;
            tp[lf1 * 4 + rh1]     = to_tf32(sacc[ni][1]);
            tp[lf1 * 4 + rh1 + 1] = to_tf32(sacc[ni][3]);
        }
        __syncwarp();

#pragma unroll
        for (int kt2 = 0; kt2 < 4; kt2++) {
            float afr[4];
            *(float4*)afr = *(float4*)&Ps[(w * 4 + kt2) * 132 + lane * 4];
#pragma unroll
            for (int ni = 0; ni < 16; ni++) {
                float bfr[2];
                *(float2*)bfr = *(float2*)&Vs[(kt2 * 16 + ni) * 68 + lane * 2];
                mma_tf32(oacc[ni], afr, bfr);
            }
        }
    }

    float inv0 = 1.0f / l0;
    float inv1 = 1.0f / l1;
    const size_t rowg = (size_t)b * T_ + (size_t)row0g;
    const size_t pglob = (rowg >> 4) * 8 + (rowg & 7);
#pragma unroll
    for (int ni = 0; ni < 16; ni++) {
        int col = h * D_ + ni * 8 + 2 * lk;
        float4 v;
        v.x = to_tf32(oacc[ni][0] * inv0);
        v.y = to_tf32(oacc[ni][2] * inv1);
        v.z = to_tf32(oacc[ni][1] * inv0);
        v.w = to_tf32(oacc[ni][3] * inv1);
        *(float4*)&g_attn[(pglob * C_ + col) * 2] = v;
    }
}

// ---------------- launch -------------------------------------------------------
extern "C" void kernel_launch(void* const* d_in, const int* in_sizes, int n_in,
                              void* d_out, int out_size)
{
    const float* x      = (const float*)d_in[0];
    const float* cosg   = (const float*)d_in[1];
    const float* sing   = (const float*)d_in[2];
    const float* W_qkv  = (const float*)d_in[3];
    const float* W_proj = (const float*)d_in[4];
    float* out = (float*)d_out;

    float* qkv;    cudaGetSymbolAddress((void**)&qkv,    g_qkv);
    float* Qb;     cudaGetSymbolAddress((void**)&Qb,     g_Q);
    float* Kb;     cudaGetSymbolAddress((void**)&Kb,     g_K);
    float* Vb;     cudaGetSymbolAddress((void**)&Vb,     g_V);
    float* attn;   cudaGetSymbolAddress((void**)&attn,   g_attn);
    float* xc;     cudaGetSymbolAddress((void**)&xc,     g_xc);
    float* wqkvC;  cudaGetSymbolAddress((void**)&wqkvC,  g_wqkvC);
    float* wprojC; cudaGetSymbolAddress((void**)&wprojC, g_wprojC);

    const int M = B_ * T_;   // 4096

    cudaFuncSetAttribute(gemm_v5_kernel,
                         cudaFuncAttributeMaxDynamicSharedMemorySize, V5_SMEM_BYTES);
    cudaFuncSetAttribute(attn_mma_kernel,
                         cudaFuncAttributeMaxDynamicSharedMemorySize,
                         ATTN_SMEM_FLOATS * sizeof(float));

    // 0) pack + tf32-round operands
    {
        int na = (M * C_) / 4;
        pack_a_kernel<<<(na + 255) / 256, 256>>>(x, xc, C_, na);
        int nbq = (C_ * 3 * C_) / 4;
        pack_b_kernel<<<(nbq + 255) / 256, 256>>>(W_qkv, wqkvC, 3 * C_, nbq);
        int nbp = (C_ * C_) / 4;
        pack_b_kernel<<<(nbp + 255) / 256, 256>>>(W_proj, wprojC, C_, nbp);
    }

    // 1) qkv = x @ W_qkv
    {
        dim3 grid(3 * C_ / V5_BN, M / V5_BM);   // (48, 32)
        gemm_v5_kernel<<<grid, 256, V5_SMEM_BYTES>>>(xc, wqkvC, qkv, M, 3 * C_, C_);
    }
    // 2) RoPE + pack K/V tiles
    {
        dim3 grid(T_ / 32, H_, B_);             // (64, 16, 2)
        rope_pack_kernel<<<grid, 256>>>(qkv, cosg, sing, Qb, Kb, Vb);
    }
    // 3) attention -> g_attn (packed-A), LPT order
    {
        dim3 grid(T_ / 64, B_ * H_);            // (32, 32)
        attn_mma_kernel<<<grid, 128, ATTN_SMEM_FLOATS * sizeof(float)>>>(Qb, Kb, Vb);
    }
    // 4) out = attn @ W_proj
    {
        dim3 grid(C_ / V5_BN, M / V5_BM);       // (16, 32)
        gemm_v5_kernel<<<grid, 256, V5_SMEM_BYTES>>>(attn, wprojC, out, M, C_, C_);
    }
}

// round 14
// speedup vs baseline: 1.0299x; 1.0091x over previous
#include <cuda_runtime.h>
#include <cstdio>
#include <cstdint>

#define B_ 2
#define T_ 2048
#define C_ 2048
#define H_ 16
#define D_ 128

// ---------------- scratch (device globals: no runtime allocation) ----------------
__device__ float g_Q[(size_t)B_ * H_ * T_ * D_];
__device__ float g_K[(size_t)B_ * H_ * T_ * D_];      // PACKED B-frag tiles
__device__ float g_V[(size_t)B_ * H_ * T_ * D_];      // PACKED B-frag tiles
__device__ float g_attn[(size_t)B_ * T_ * C_];        // PACKED-A layout
__device__ float g_xc[(size_t)B_ * T_ * C_];          // packed-A tf32 x
__device__ float g_wqkvC[(size_t)C_ * 3 * C_];        // packed-B tf32 W_qkv
__device__ float g_wprojC[(size_t)C_ * C_];           // packed-B tf32 W_proj

// ---------------- helpers -------------------------------------------------------
__device__ __forceinline__ float to_tf32(float x) {
    unsigned u;
    asm("cvt.rna.tf32.f32 %0, %1;" : "=r"(u) : "f"(x));
    return __uint_as_float(u);
}

__device__ __forceinline__ void mma_tf32(float c[4], const float a[4], const float b[2]) {
    asm volatile(
        "mma.sync.aligned.m16n8k8.row.col.f32.tf32.tf32.f32 "
        "{%0,%1,%2,%3}, {%4,%5,%6,%7}, {%8,%9}, {%0,%1,%2,%3};"
        : "+f"(c[0]), "+f"(c[1]), "+f"(c[2]), "+f"(c[3])
        : "r"(__float_as_uint(a[0])), "r"(__float_as_uint(a[1])),
          "r"(__float_as_uint(a[2])), "r"(__float_as_uint(a[3])),
          "r"(__float_as_uint(b[0])), "r"(__float_as_uint(b[1])));
}

__device__ __forceinline__ uint32_t smem_u32(const void* p) {
    uint32_t a;
    asm("{ .reg .u64 t; cvta.to.shared.u64 t, %1; cvt.u32.u64 %0, t; }" : "=r"(a) : "l"(p));
    return a;
}

#define CP_ASYNC16(dst, src) \
    asm volatile("cp.async.cg.shared.global [%0], [%1], 16;" :: "r"(dst), "l"(src) : "memory")
#define CP_COMMIT() asm volatile("cp.async.commit_group;" ::: "memory")

// ============ GEMM v6: packed operands + optional fused RoPE/pack epilogue ======
#define V5_BM 128
#define V5_BN 128
#define V5_BK 32
#define V5_ASTR 72
#define V5_BSTR 264
#define V5_AFLOATS (64 * V5_ASTR)             // 4608
#define V5_BFLOATS (16 * V5_BSTR)             // 4224
#define V5_STAGEF (V5_AFLOATS + V5_BFLOATS)   // 8832 floats
#define V5_NST 3
#define V5_SMEM_BYTES (V5_NST * V5_STAGEF * 4)  // 105984

// mode 0: plain row-major C write (proj).  mode 1: fused qkv epilogue.
__global__ __launch_bounds__(256, 2) void gemm_v6_kernel(
    const float* __restrict__ Ap, const float* __restrict__ Bp, float* __restrict__ Cm,
    const float* __restrict__ cosg, const float* __restrict__ sing,
    float* __restrict__ Qout, float* __restrict__ Kout, float* __restrict__ Vout,
    int M, int N, int K, int mode)
{
    extern __shared__ float sm[];

    const int tid = threadIdx.x;
    const int warp = tid >> 5;
    const int lane = tid & 31;
    const int lm = lane >> 2;
    const int lk = lane & 3;

    const int m0 = blockIdx.y * V5_BM;
    const int n0 = blockIdx.x * V5_BN;
    const int wm = (warp >> 2) * 64;
    const int wn = (warp & 3) * 32;

    const uint32_t smb = smem_u32(sm);

    float acc[4][4][4];
#pragma unroll
    for (int mi = 0; mi < 4; mi++)
#pragma unroll
        for (int ni = 0; ni < 4; ni++)
#pragma unroll
            for (int r = 0; r < 4; r++) acc[mi][ni][r] = 0.0f;

    auto load_stage = [&](int s) {
        const int k0 = s * V5_BK;
        const uint32_t base = smb + (uint32_t)((s % V5_NST) * V5_STAGEF * 4);
#pragma unroll
        for (int i = 0; i < 4; i++) {
            int id = tid + i * 256;
            int p = id >> 4, kc = id & 15;
            uint32_t dst = base + (uint32_t)((p * V5_ASTR + kc * 4) * 4);
            const float* src = Ap + ((size_t)(m0 / 2 + p) * K + k0 + kc * 2) * 2;
            CP_ASYNC16(dst, src);
        }
        const uint32_t bbase = base + V5_AFLOATS * 4;
#pragma unroll
        for (int i = 0; i < 4; i++) {
            int id = tid + i * 256;
            int kp = id >> 6, nc = id & 63;
            uint32_t dst = bbase + (uint32_t)((kp * V5_BSTR + nc * 4) * 4);
            const float* src = Bp + ((size_t)(k0 / 2 + kp) * N + n0 + nc * 2) * 2;
            CP_ASYNC16(dst, src);
        }
        CP_COMMIT();
    };

    const int nst = K / V5_BK;   // 64
    load_stage(0);
    load_stage(1);

    for (int ks = 0; ks < nst; ks++) {
        asm volatile("cp.async.wait_group %0;" :: "n"(1) : "memory");
        __syncthreads();

        const float* As = sm + (size_t)(ks % V5_NST) * V5_STAGEF;
        const float* Bs = As + V5_AFLOATS;

#pragma unroll
        for (int kk = 0; kk < V5_BK; kk += 8) {
            float afr[4][4];
#pragma unroll
            for (int mi = 0; mi < 4; mi++) {
                int aw = (((wm >> 4) + mi) * 8 + lm) * V5_ASTR + (kk + lk) * 2;
                *(float2*)&afr[mi][0] = *(const float2*)&As[aw];
                *(float2*)&afr[mi][2] = *(const float2*)&As[aw + 8];
            }
            float bfr[4][2];
#pragma unroll
            for (int ni = 0; ni < 4; ni++) {
                int bw = ((kk >> 3) * 4 + lk) * V5_BSTR + (wn + ni * 8 + lm) * 2;
                *(float2*)&bfr[ni][0] = *(const float2*)&Bs[bw];
            }
#pragma unroll
            for (int mi = 0; mi < 4; mi++)
#pragma unroll
                for (int ni = 0; ni < 4; ni++)
                    mma_tf32(acc[mi][ni], afr[mi], bfr[ni]);
        }

        if (ks + 2 < nst) load_stage(ks + 2);
        else CP_COMMIT();
    }

    if (mode == 0) {
        // plain row-major epilogue (proj)
#pragma unroll
        for (int mi = 0; mi < 4; mi++) {
#pragma unroll
            for (int ni = 0; ni < 4; ni++) {
                int gr = m0 + wm + mi * 16 + lm;
                int gc = n0 + wn + ni * 8 + lk * 2;
                float* p0 = Cm + (size_t)gr * N + gc;
                float* p1 = Cm + (size_t)(gr + 8) * N + gc;
                *(float2*)p0 = make_float2(acc[mi][ni][0], acc[mi][ni][1]);
                *(float2*)p1 = make_float2(acc[mi][ni][2], acc[mi][ni][3]);
            }
        }
        return;
    }

    // ---- fused qkv epilogue: stage tile into smem, then rope/pack per type ----
    float* Ct = sm;                    // [128][132]
    float* stP = sm + 128 * 132;       // 4096 floats
    __syncthreads();                   // all warps done reading stage buffers
#pragma unroll
    for (int mi = 0; mi < 4; mi++) {
#pragma unroll
        for (int ni = 0; ni < 4; ni++) {
            int rr = wm + mi * 16 + lm;
            int cc = wn + ni * 8 + lk * 2;
            *(float2*)&Ct[rr * 132 + cc] = make_float2(acc[mi][ni][0], acc[mi][ni][1]);
            *(float2*)&Ct[(rr + 8) * 132 + cc] = make_float2(acc[mi][ni][2], acc[mi][ni][3]);
        }
    }
    __syncthreads();

    const int type = n0 >> 11;           // 0:Q 1:K 2:V
    const int h = (n0 & 2047) >> 7;
    const int b = m0 >> 11;
    const int t0 = m0 & 2047;
    const size_t bh = (size_t)(b * H_ + h);

    if (type == 0) {
        // Q: rope, row-major [bh, t, d]
#pragma unroll
        for (int i = 0; i < 32; i++) {
            int idx = tid + i * 256;
            int r = idx >> 6, d = idx & 63;
            int t = t0 + r;
            float c = cosg[t * 64 + d];
            float s = sing[t * 64 + d];
            float q1 = Ct[r * 132 + d];
            float q2 = Ct[r * 132 + d + 64];
            float* Qrow = Qout + (bh * T_ + t) * D_;
            Qrow[d]      = q1 * c - q2 * s;
            Qrow[d + 64] = q1 * s + q2 * c;
        }
    } else if (type == 1) {
        // K: rope + tf32 + packed B-frag tiles (4 subtiles of 32 rows)
        for (int st = 0; st < 4; st++) {
#pragma unroll
            for (int i = 0; i < 8; i++) {
                int idx = tid + i * 256;
                int r = idx >> 6, d = idx & 63;
                int t = t0 + st * 32 + r;
                float c = cosg[t * 64 + d];
                float s = sing[t * 64 + d];
                float k1 = Ct[(st * 32 + r) * 132 + d];
                float k2 = Ct[(st * 32 + r) * 132 + d + 64];
                float kr1 = to_tf32(k1 * c - k2 * s);
                float kr2 = to_tf32(k1 * s + k2 * c);
                stP[((r >> 3) * 16 + (d >> 3)) * 64 + ((r & 7) * 4 + (d & 3)) * 2 + ((d >> 2) & 1)] = kr1;
                int d2 = d + 64;
                stP[((r >> 3) * 16 + (d2 >> 3)) * 64 + ((r & 7) * 4 + (d2 & 3)) * 2 + ((d2 >> 2) & 1)] = kr2;
            }
            __syncthreads();
            float* kout = Kout + bh * ((size_t)T_ * D_) + (size_t)(t0 / 32 + st) * 4096;
#pragma unroll
            for (int i = 0; i < 4; i++) {
                int c2 = tid + i * 256;
                *(float4*)(kout + c2 * 4) = *(const float4*)(stP + c2 * 4);
            }
            __syncthreads();
        }
    } else {
        // V: tf32 + packed tiles
        for (int st = 0; st < 4; st++) {
#pragma unroll
            for (int i = 0; i < 16; i++) {
                int idx = tid + i * 256;
                int r = idx >> 7, d = idx & 127;
                float v = to_tf32(Ct[(st * 32 + r) * 132 + d]);
                stP[((r >> 3) * 16 + (d >> 3)) * 64 + ((d & 7) * 4 + (r & 3)) * 2 + ((r >> 2) & 1)] = v;
            }
            __syncthreads();
            float* vout = Vout + bh * ((size_t)T_ * D_) + (size_t)(t0 / 32 + st) * 4096;
#pragma unroll
            for (int i = 0; i < 4; i++) {
                int c2 = tid + i * 256;
                *(float4*)(vout + c2 * 4) = *(const float4*)(stP + c2 * 4);
            }
            __syncthreads();
        }
    }
}

// ---------------- pack pre-passes (tf32-round + layout) -------------------------
__global__ __launch_bounds__(256) void pack_a_kernel(
    const float* __restrict__ src, float* __restrict__ dst, int K, int nchunk)
{
    int c = blockIdx.x * blockDim.x + threadIdx.x;
    if (c >= nchunk) return;
    int kh = K >> 1;
    int p = c / kh, kc = c - p * kh;
    int m = (p >> 3) * 16 + (p & 7);
    int k = kc * 2;
    const float* r0 = src + (size_t)m * K + k;
    const float* r1 = r0 + (size_t)8 * K;
    float4 v;
    v.x = to_tf32(r0[0]); v.y = to_tf32(r1[0]);
    v.z = to_tf32(r0[1]); v.w = to_tf32(r1[1]);
    *(float4*)(dst + (size_t)c * 4) = v;
}

__global__ __launch_bounds__(256) void pack_b_kernel(
    const float* __restrict__ src, float* __restrict__ dst, int N, int nchunk)
{
    int c = blockIdx.x * blockDim.x + threadIdx.x;
    if (c >= nchunk) return;
    int nh = N >> 1;
    int kp = c / nh, nc = c - kp * nh;
    int k = (kp >> 2) * 8 + (kp & 3);
    int n = nc * 2;
    const float* r0 = src + (size_t)k * N + n;
    const float* r1 = r0 + (size_t)4 * N;
    float4 v;
    v.x = to_tf32(r0[0]); v.y = to_tf32(r1[0]);
    v.z = to_tf32(r0[1]); v.w = to_tf32(r1[1]);
    *(float4*)(dst + (size_t)c * 4) = v;
}

// ---------------- attention v3b: LPT order, Q in regs, cp.async packed K/V ------
#define KV_TILE_F (64 * 68)
#define PS_FLOATS (16 * 132)
#define ATTN_SMEM_FLOATS (2 * 2 * KV_TILE_F + PS_FLOATS)   // 78080 B

__global__ __launch_bounds__(128, 2) void attn_mma_kernel(
    const float* __restrict__ Q, const float* __restrict__ Kp,
    const float* __restrict__ Vp)
{
    extern __shared__ float sm[];
    float* Ps = sm + 2 * 2 * KV_TILE_F;

    const int qb = (int)gridDim.x - 1 - (int)blockIdx.x;
    const int bh = blockIdx.y;
    const int b = bh >> 4;
    const int h = bh & 15;
    const int tid = threadIdx.x;
    const int w = tid >> 5;
    const int lane = tid & 31;
    const int lm = lane >> 2;
    const int lk = lane & 3;
    const int q0 = qb * 64;

    const float* Qg = Q + ((size_t)bh * T_ + q0) * D_;
    const float* Kg = Kp + (size_t)bh * T_ * D_;
    const float* Vg = Vp + (size_t)bh * T_ * D_;
    const uint32_t smb = smem_u32(sm);

    const int row0g = q0 + w * 16 + lm;
    const int row1g = row0g + 8;

    float qfr[16][4];
    {
        const float* q0p = Qg + (size_t)(w * 16 + lm) * D_;
        const float* q1p = q0p + 8 * D_;
#pragma unroll
        for (int dk = 0; dk < 16; dk++) {
            int col = dk * 8 + lk;
            qfr[dk][0] = to_tf32(q0p[col]);
            qfr[dk][1] = to_tf32(q1p[col]);
            qfr[dk][2] = to_tf32(q0p[col + 4]);
            qfr[dk][3] = to_tf32(q1p[col + 4]);
        }
    }

    float m0 = -1e30f, m1 = -1e30f, l0 = 0.0f, l1 = 0.0f;
    float oacc[16][4];
#pragma unroll
    for (int ni = 0; ni < 16; ni++)
#pragma unroll
        for (int r = 0; r < 4; r++) oacc[ni][r] = 0.0f;

    const float scale = 0.08838834764831845f;
    const int nkv = (q0 + 64) / 32;

    auto load_kv = [&](int kt) {
        const uint32_t dstb = smb + (uint32_t)((kt & 1) * 2 * KV_TILE_F * 4);
        const float* ksrc = Kg + (size_t)kt * 4096;
        const float* vsrc = Vg + (size_t)kt * 4096;
#pragma unroll
        for (int i = 0; i < 8; i++) {
            int c = tid + i * 128;
            int sub = c >> 4, q = c & 15;
            uint32_t off = (uint32_t)((sub * 68 + q * 4) * 4);
            CP_ASYNC16(dstb + off, ksrc + c * 4);
            CP_ASYNC16(dstb + KV_TILE_F * 4 + off, vsrc + c * 4);
        }
        CP_COMMIT();
    };

    load_kv(0);

    for (int kt = 0; kt < nkv; kt++) {
        const int kv0 = kt * 32;
        asm volatile("cp.async.wait_group 0;" ::: "memory");
        __syncthreads();
        if (kt + 1 < nkv) load_kv(kt + 1);

        const float* Ks = sm + (kt & 1) * 2 * KV_TILE_F;
        const float* Vs = Ks + KV_TILE_F;

        float sacc[4][4];
#pragma unroll
        for (int ni = 0; ni < 4; ni++)
#pragma unroll
            for (int r = 0; r < 4; r++) sacc[ni][r] = 0.0f;

#pragma unroll
        for (int dk = 0; dk < 16; dk++) {
#pragma unroll
            for (int ni = 0; ni < 4; ni++) {
                float bfr[2];
                *(float2*)bfr = *(float2*)&Ks[(ni * 16 + dk) * 68 + lane * 2];
                mma_tf32(sacc[ni], qfr[dk], bfr);
            }
        }

        const bool needMask = (kt >= 2 * qb);
#pragma unroll
        for (int ni = 0; ni < 4; ni++) {
            int c0 = kv0 + ni * 8 + 2 * lk;
#pragma unroll
            for (int r = 0; r < 4; r++) sacc[ni][r] *= scale;
            if (needMask) {
                if (c0     > row0g) sacc[ni][0] = -1e30f;
                if (c0 + 1 > row0g) sacc[ni][1] = -1e30f;
                if (c0     > row1g) sacc[ni][2] = -1e30f;
                if (c0 + 1 > row1g) sacc[ni][3] = -1e30f;
            }
        }

        float rmax0 = -1e30f, rmax1 = -1e30f;
#pragma unroll
        for (int ni = 0; ni < 4; ni++) {
            rmax0 = fmaxf(rmax0, fmaxf(sacc[ni][0], sacc[ni][1]));
            rmax1 = fmaxf(rmax1, fmaxf(sacc[ni][2], sacc[ni][3]));
        }
        rmax0 = fmaxf(rmax0, __shfl_xor_sync(0xffffffffu, rmax0, 1));
        rmax0 = fmaxf(rmax0, __shfl_xor_sync(0xffffffffu, rmax0, 2));
        rmax1 = fmaxf(rmax1, __shfl_xor_sync(0xffffffffu, rmax1, 1));
        rmax1 = fmaxf(rmax1, __shfl_xor_sync(0xffffffffu, rmax1, 2));
        float mn0 = fmaxf(m0, rmax0);
        float mn1 = fmaxf(m1, rmax1);
        float al0 = __expf(m0 - mn0);
        float al1 = __expf(m1 - mn1);
        float rs0 = 0.0f, rs1 = 0.0f;
#pragma unroll
        for (int ni = 0; ni < 4; ni++) {
            sacc[ni][0] = __expf(sacc[ni][0] - mn0);
            sacc[ni][1] = __expf(sacc[ni][1] - mn0);
            sacc[ni][2] = __expf(sacc[ni][2] - mn1);
            sacc[ni][3] = __expf(sacc[ni][3] - mn1);
            rs0 += sacc[ni][0] + sacc[ni][1];
            rs1 += sacc[ni][2] + sacc[ni][3];
        }
        rs0 += __shfl_xor_sync(0xffffffffu, rs0, 1);
        rs0 += __shfl_xor_sync(0xffffffffu, rs0, 2);
        rs1 += __shfl_xor_sync(0xffffffffu, rs1, 1);
        rs1 += __shfl_xor_sync(0xffffffffu, rs1, 2);
        l0 = l0 * al0 + rs0;
        l1 = l1 * al1 + rs1;
        m0 = mn0;
        m1 = mn1;
#pragma unroll
        for (int ni = 0; ni < 16; ni++) {
            oacc[ni][0] *= al0; oacc[ni][1] *= al0;
            oacc[ni][2] *= al1; oacc[ni][3] *= al1;
        }

#pragma unroll
        for (int ni = 0; ni < 4; ni++) {
            float* tp = &Ps[(w * 4 + ni) * 132];
            int c0 = 2 * lk;
            int lf0 = (lm << 2) | (c0 & 3);
            int rh0 = (c0 >= 4) ? 2 : 0;
            tp[lf0 * 4 + rh0]     = to_tf32(sacc[ni][0]);
            tp[lf0 * 4 + rh0 + 1] = to_tf32(sacc[ni][2]);
            int c1 = 2 * lk + 1;
            int lf1 = (lm << 2) | (c1 & 3);
            int rh1 = (c1 >= 4) ? 2 : 0;
            tp[lf1 * 4 + rh1]     = to_tf32(sacc[ni][1]);
            tp[lf1 * 4 + rh1 + 1] = to_tf32(sacc[ni][3]);
        }
        __syncwarp();

#pragma unroll
        for (int kt2 = 0; kt2 < 4; kt2++) {
            float afr[4];
            *(float4*)afr = *(float4*)&Ps[(w * 4 + kt2) * 132 + lane * 4];
#pragma unroll
            for (int ni = 0; ni < 16; ni++) {
                float bfr[2];
                *(float2*)bfr = *(float2*)&Vs[(kt2 * 16 + ni) * 68 + lane * 2];
                mma_tf32(oacc[ni], afr, bfr);
            }
        }
    }

    float inv0 = 1.0f / l0;
    float inv1 = 1.0f / l1;
    const size_t rowg = (size_t)b * T_ + (size_t)row0g;
    const size_t pglob = (rowg >> 4) * 8 + (rowg & 7);
#pragma unroll
    for (int ni = 0; ni < 16; ni++) {
        int col = h * D_ + ni * 8 + 2 * lk;
        float4 v;
        v.x = to_tf32(oacc[ni][0] * inv0);
        v.y = to_tf32(oacc[ni][2] * inv1);
        v.z = to_tf32(oacc[ni][1] * inv0);
        v.w = to_tf32(oacc[ni][3] * inv1);
        *(float4*)&g_attn[(pglob * C_ + col) * 2] = v;
    }
}

// ---------------- launch -------------------------------------------------------
extern "C" void kernel_launch(void* const* d_in, const int* in_sizes, int n_in,
                              void* d_out, int out_size)
{
    const float* x      = (const float*)d_in[0];
    const float* cosg   = (const float*)d_in[1];
    const float* sing   = (const float*)d_in[2];
    const float* W_qkv  = (const float*)d_in[3];
    const float* W_proj = (const float*)d_in[4];
    float* out = (float*)d_out;

    float* Qb;     cudaGetSymbolAddress((void**)&Qb,     g_Q);
    float* Kb;     cudaGetSymbolAddress((void**)&Kb,     g_K);
    float* Vb;     cudaGetSymbolAddress((void**)&Vb,     g_V);
    float* attn;   cudaGetSymbolAddress((void**)&attn,   g_attn);
    float* xc;     cudaGetSymbolAddress((void**)&xc,     g_xc);
    float* wqkvC;  cudaGetSymbolAddress((void**)&wqkvC,  g_wqkvC);
    float* wprojC; cudaGetSymbolAddress((void**)&wprojC, g_wprojC);

    const int M = B_ * T_;   // 4096

    cudaFuncSetAttribute(gemm_v6_kernel,
                         cudaFuncAttributeMaxDynamicSharedMemorySize, V5_SMEM_BYTES);
    cudaFuncSetAttribute(attn_mma_kernel,
                         cudaFuncAttributeMaxDynamicSharedMemorySize,
                         ATTN_SMEM_FLOATS * sizeof(float));

    // 0) pack + tf32-round operands
    {
        int na = (M * C_) / 4;
        pack_a_kernel<<<(na + 255) / 256, 256>>>(x, xc, C_, na);
        int nbq = (C_ * 3 * C_) / 4;
        pack_b_kernel<<<(nbq + 255) / 256, 256>>>(W_qkv, wqkvC, 3 * C_, nbq);
        int nbp = (C_ * C_) / 4;
        pack_b_kernel<<<(nbp + 255) / 256, 256>>>(W_proj, wprojC, C_, nbp);
    }

    // 1) qkv GEMM with fused RoPE/pack epilogue -> g_Q / g_K / g_V directly
    {
        dim3 grid(3 * C_ / V5_BN, M / V5_BM);   // (48, 32)
        gemm_v6_kernel<<<grid, 256, V5_SMEM_BYTES>>>(
            xc, wqkvC, nullptr, cosg, sing, Qb, Kb, Vb, M, 3 * C_, C_, 1);
    }
    // 2) attention -> g_attn (packed-A), LPT order
    {
        dim3 grid(T_ / 64, B_ * H_);            // (32, 32)
        attn_mma_kernel<<<grid, 128, ATTN_SMEM_FLOATS * sizeof(float)>>>(Qb, Kb, Vb);
    }
    // 3) out = attn @ W_proj (plain epilogue)
    {
        dim3 grid(C_ / V5_BN, M / V5_BM);       // (16, 32)
        gemm_v6_kernel<<<grid, 256, V5_SMEM_BYTES>>>(
            attn, wprojC, out, nullptr, nullptr, nullptr, nullptr, nullptr,
            M, C_, C_, 0);
    }
}

// round 15
// speedup vs baseline: 1.0344x; 1.0044x over previous
#include <cuda_runtime.h>
#include <cstdio>
#include <cstdint>

#define B_ 2
#define T_ 2048
#define C_ 2048
#define H_ 16
#define D_ 128

// ---------------- scratch (device globals: no runtime allocation) ----------------
__device__ float g_Q[(size_t)B_ * H_ * T_ * D_];
__device__ float g_K[(size_t)B_ * H_ * T_ * D_];      // PACKED B-frag tiles
__device__ float g_V[(size_t)B_ * H_ * T_ * D_];      // PACKED B-frag tiles
__device__ float g_attn[(size_t)B_ * T_ * C_];        // PACKED-A layout
__device__ float g_xc[(size_t)B_ * T_ * C_];          // packed-A tf32 x
__device__ float g_wqkvC[(size_t)C_ * 3 * C_];        // packed-B tf32 W_qkv
__device__ float g_wprojC[(size_t)C_ * C_];           // packed-B tf32 W_proj

// ---------------- helpers -------------------------------------------------------
__device__ __forceinline__ float to_tf32(float x) {
    unsigned u;
    asm("cvt.rna.tf32.f32 %0, %1;" : "=r"(u) : "f"(x));
    return __uint_as_float(u);
}

__device__ __forceinline__ void mma_tf32(float c[4], const float a[4], const float b[2]) {
    asm volatile(
        "mma.sync.aligned.m16n8k8.row.col.f32.tf32.tf32.f32 "
        "{%0,%1,%2,%3}, {%4,%5,%6,%7}, {%8,%9}, {%0,%1,%2,%3};"
        : "+f"(c[0]), "+f"(c[1]), "+f"(c[2]), "+f"(c[3])
        : "r"(__float_as_uint(a[0])), "r"(__float_as_uint(a[1])),
          "r"(__float_as_uint(a[2])), "r"(__float_as_uint(a[3])),
          "r"(__float_as_uint(b[0])), "r"(__float_as_uint(b[1])));
}

__device__ __forceinline__ uint32_t smem_u32(const void* p) {
    uint32_t a;
    asm("{ .reg .u64 t; cvta.to.shared.u64 t, %1; cvt.u32.u64 %0, t; }" : "=r"(a) : "l"(p));
    return a;
}

#define CP_ASYNC16(dst, src) \
    asm volatile("cp.async.cg.shared.global [%0], [%1], 16;" :: "r"(dst), "l"(src) : "memory")
#define CP_COMMIT() asm volatile("cp.async.commit_group;" ::: "memory")

// ============ GEMM v6: packed operands + optional fused RoPE/pack epilogue ======
#define V5_BM 128
#define V5_BN 128
#define V5_BK 32
#define V5_ASTR 72
#define V5_BSTR 264
#define V5_AFLOATS (64 * V5_ASTR)             // 4608
#define V5_BFLOATS (16 * V5_BSTR)             // 4224
#define V5_STAGEF (V5_AFLOATS + V5_BFLOATS)   // 8832 floats
#define V5_NST 3
#define V5_SMEM_BYTES (V5_NST * V5_STAGEF * 4)  // 105984

// mode 0: plain row-major C write (proj).  mode 1: fused qkv epilogue.
__global__ __launch_bounds__(256, 2) void gemm_v6_kernel(
    const float* __restrict__ Ap, const float* __restrict__ Bp, float* __restrict__ Cm,
    const float* __restrict__ cosg, const float* __restrict__ sing,
    float* __restrict__ Qout, float* __restrict__ Kout, float* __restrict__ Vout,
    int M, int N, int K, int mode)
{
    extern __shared__ float sm[];

    const int tid = threadIdx.x;
    const int warp = tid >> 5;
    const int lane = tid & 31;
    const int lm = lane >> 2;
    const int lk = lane & 3;

    const int m0 = blockIdx.y * V5_BM;
    const int n0 = blockIdx.x * V5_BN;
    const int wm = (warp >> 2) * 64;
    const int wn = (warp & 3) * 32;

    const uint32_t smb = smem_u32(sm);

    float acc[4][4][4];
#pragma unroll
    for (int mi = 0; mi < 4; mi++)
#pragma unroll
        for (int ni = 0; ni < 4; ni++)
#pragma unroll
            for (int r = 0; r < 4; r++) acc[mi][ni][r] = 0.0f;

    auto load_stage = [&](int s) {
        const int k0 = s * V5_BK;
        const uint32_t base = smb + (uint32_t)((s % V5_NST) * V5_STAGEF * 4);
#pragma unroll
        for (int i = 0; i < 4; i++) {
            int id = tid + i * 256;
            int p = id >> 4, kc = id & 15;
            uint32_t dst = base + (uint32_t)((p * V5_ASTR + kc * 4) * 4);
            const float* src = Ap + ((size_t)(m0 / 2 + p) * K + k0 + kc * 2) * 2;
            CP_ASYNC16(dst, src);
        }
        const uint32_t bbase = base + V5_AFLOATS * 4;
#pragma unroll
        for (int i = 0; i < 4; i++) {
            int id = tid + i * 256;
            int kp = id >> 6, nc = id & 63;
            uint32_t dst = bbase + (uint32_t)((kp * V5_BSTR + nc * 4) * 4);
            const float* src = Bp + ((size_t)(k0 / 2 + kp) * N + n0 + nc * 2) * 2;
            CP_ASYNC16(dst, src);
        }
        CP_COMMIT();
    };

    const int nst = K / V5_BK;   // 64
    load_stage(0);
    load_stage(1);

    for (int ks = 0; ks < nst; ks++) {
        asm volatile("cp.async.wait_group %0;" :: "n"(1) : "memory");
        __syncthreads();

        const float* As = sm + (size_t)(ks % V5_NST) * V5_STAGEF;
        const float* Bs = As + V5_AFLOATS;

#pragma unroll
        for (int kk = 0; kk < V5_BK; kk += 8) {
            float afr[4][4];
#pragma unroll
            for (int mi = 0; mi < 4; mi++) {
                int aw = (((wm >> 4) + mi) * 8 + lm) * V5_ASTR + (kk + lk) * 2;
                *(float2*)&afr[mi][0] = *(const float2*)&As[aw];
                *(float2*)&afr[mi][2] = *(const float2*)&As[aw + 8];
            }
            float bfr[4][2];
#pragma unroll
            for (int ni = 0; ni < 4; ni++) {
                int bw = ((kk >> 3) * 4 + lk) * V5_BSTR + (wn + ni * 8 + lm) * 2;
                *(float2*)&bfr[ni][0] = *(const float2*)&Bs[bw];
            }
#pragma unroll
            for (int mi = 0; mi < 4; mi++)
#pragma unroll
                for (int ni = 0; ni < 4; ni++)
                    mma_tf32(acc[mi][ni], afr[mi], bfr[ni]);
        }

        if (ks + 2 < nst) load_stage(ks + 2);
        else CP_COMMIT();
    }

    if (mode == 0) {
#pragma unroll
        for (int mi = 0; mi < 4; mi++) {
#pragma unroll
            for (int ni = 0; ni < 4; ni++) {
                int gr = m0 + wm + mi * 16 + lm;
                int gc = n0 + wn + ni * 8 + lk * 2;
                float* p0 = Cm + (size_t)gr * N + gc;
                float* p1 = Cm + (size_t)(gr + 8) * N + gc;
                *(float2*)p0 = make_float2(acc[mi][ni][0], acc[mi][ni][1]);
                *(float2*)p1 = make_float2(acc[mi][ni][2], acc[mi][ni][3]);
            }
        }
        return;
    }

    // ---- fused qkv epilogue ----
    float* Ct = sm;                    // [128][132]
    float* stP = sm + 128 * 132;       // 4096 floats
    __syncthreads();
#pragma unroll
    for (int mi = 0; mi < 4; mi++) {
#pragma unroll
        for (int ni = 0; ni < 4; ni++) {
            int rr = wm + mi * 16 + lm;
            int cc = wn + ni * 8 + lk * 2;
            *(float2*)&Ct[rr * 132 + cc] = make_float2(acc[mi][ni][0], acc[mi][ni][1]);
            *(float2*)&Ct[(rr + 8) * 132 + cc] = make_float2(acc[mi][ni][2], acc[mi][ni][3]);
        }
    }
    __syncthreads();

    const int type = n0 >> 11;           // 0:Q 1:K 2:V
    const int h = (n0 & 2047) >> 7;
    const int b = m0 >> 11;
    const int t0 = m0 & 2047;
    const size_t bh = (size_t)(b * H_ + h);

    if (type == 0) {
#pragma unroll
        for (int i = 0; i < 32; i++) {
            int idx = tid + i * 256;
            int r = idx >> 6, d = idx & 63;
            int t = t0 + r;
            float c = cosg[t * 64 + d];
            float s = sing[t * 64 + d];
            float q1 = Ct[r * 132 + d];
            float q2 = Ct[r * 132 + d + 64];
            float* Qrow = Qout + (bh * T_ + t) * D_;
            Qrow[d]      = q1 * c - q2 * s;
            Qrow[d + 64] = q1 * s + q2 * c;
        }
    } else if (type == 1) {
        for (int st = 0; st < 4; st++) {
#pragma unroll
            for (int i = 0; i < 8; i++) {
                int idx = tid + i * 256;
                int r = idx >> 6, d = idx & 63;
                int t = t0 + st * 32 + r;
                float c = cosg[t * 64 + d];
                float s = sing[t * 64 + d];
                float k1 = Ct[(st * 32 + r) * 132 + d];
                float k2 = Ct[(st * 32 + r) * 132 + d + 64];
                float kr1 = to_tf32(k1 * c - k2 * s);
                float kr2 = to_tf32(k1 * s + k2 * c);
                stP[((r >> 3) * 16 + (d >> 3)) * 64 + ((r & 7) * 4 + (d & 3)) * 2 + ((d >> 2) & 1)] = kr1;
                int d2 = d + 64;
                stP[((r >> 3) * 16 + (d2 >> 3)) * 64 + ((r & 7) * 4 + (d2 & 3)) * 2 + ((d2 >> 2) & 1)] = kr2;
            }
            __syncthreads();
            float* kout = Kout + bh * ((size_t)T_ * D_) + (size_t)(t0 / 32 + st) * 4096;
#pragma unroll
            for (int i = 0; i < 4; i++) {
                int c2 = tid + i * 256;
                *(float4*)(kout + c2 * 4) = *(const float4*)(stP + c2 * 4);
            }
            __syncthreads();
        }
    } else {
        for (int st = 0; st < 4; st++) {
#pragma unroll
            for (int i = 0; i < 16; i++) {
                int idx = tid + i * 256;
                int r = idx >> 7, d = idx & 127;
                float v = to_tf32(Ct[(st * 32 + r) * 132 + d]);
                stP[((r >> 3) * 16 + (d >> 3)) * 64 + ((d & 7) * 4 + (r & 3)) * 2 + ((r >> 2) & 1)] = v;
            }
            __syncthreads();
            float* vout = Vout + bh * ((size_t)T_ * D_) + (size_t)(t0 / 32 + st) * 4096;
#pragma unroll
            for (int i = 0; i < 4; i++) {
                int c2 = tid + i * 256;
                *(float4*)(vout + c2 * 4) = *(const float4*)(stP + c2 * 4);
            }
            __syncthreads();
        }
    }
}

// ---------------- pack pre-passes (tf32-round + layout) -------------------------
__global__ __launch_bounds__(256) void pack_a_kernel(
    const float* __restrict__ src, float* __restrict__ dst, int K, int nchunk)
{
    int c = blockIdx.x * blockDim.x + threadIdx.x;
    if (c >= nchunk) return;
    int kh = K >> 1;
    int p = c / kh, kc = c - p * kh;
    int m = (p >> 3) * 16 + (p & 7);
    int k = kc * 2;
    const float* r0 = src + (size_t)m * K + k;
    const float* r1 = r0 + (size_t)8 * K;
    float4 v;
    v.x = to_tf32(r0[0]); v.y = to_tf32(r1[0]);
    v.z = to_tf32(r0[1]); v.w = to_tf32(r1[1]);
    *(float4*)(dst + (size_t)c * 4) = v;
}

__global__ __launch_bounds__(256) void pack_b_kernel(
    const float* __restrict__ src, float* __restrict__ dst, int N, int nchunk)
{
    int c = blockIdx.x * blockDim.x + threadIdx.x;
    if (c >= nchunk) return;
    int nh = N >> 1;
    int kp = c / nh, nc = c - kp * nh;
    int k = (kp >> 2) * 8 + (kp & 3);
    int n = nc * 2;
    const float* r0 = src + (size_t)k * N + n;
    const float* r1 = r0 + (size_t)4 * N;
    float4 v;
    v.x = to_tf32(r0[0]); v.y = to_tf32(r1[0]);
    v.z = to_tf32(r0[1]); v.w = to_tf32(r1[1]);
    *(float4*)(dst + (size_t)c * 4) = v;
}

// ---------------- attention v4: shuffle P-transpose (no Ps smem) ----------------
#define KV_TILE_F (64 * 68)
#define ATTN_SMEM_FLOATS (2 * 2 * KV_TILE_F)   // 69632 B

__global__ __launch_bounds__(128, 2) void attn_mma_kernel(
    const float* __restrict__ Q, const float* __restrict__ Kp,
    const float* __restrict__ Vp)
{
    extern __shared__ float sm[];

    const int qb = (int)gridDim.x - 1 - (int)blockIdx.x;   // LPT
    const int bh = blockIdx.y;
    const int b = bh >> 4;
    const int h = bh & 15;
    const int tid = threadIdx.x;
    const int w = tid >> 5;
    const int lane = tid & 31;
    const int lm = lane >> 2;
    const int lk = lane & 3;
    const int q0 = qb * 64;

    const float* Qg = Q + ((size_t)bh * T_ + q0) * D_;
    const float* Kg = Kp + (size_t)bh * T_ * D_;
    const float* Vg = Vp + (size_t)bh * T_ * D_;
    const uint32_t smb = smem_u32(sm);

    const int row0g = q0 + w * 16 + lm;
    const int row1g = row0g + 8;

    float qfr[16][4];
    {
        const float* q0p = Qg + (size_t)(w * 16 + lm) * D_;
        const float* q1p = q0p + 8 * D_;
#pragma unroll
        for (int dk = 0; dk < 16; dk++) {
            int col = dk * 8 + lk;
            qfr[dk][0] = to_tf32(q0p[col]);
            qfr[dk][1] = to_tf32(q1p[col]);
            qfr[dk][2] = to_tf32(q0p[col + 4]);
            qfr[dk][3] = to_tf32(q1p[col + 4]);
        }
    }

    float m0 = -1e30f, m1 = -1e30f, l0 = 0.0f, l1 = 0.0f;
    float oacc[16][4];
#pragma unroll
    for (int ni = 0; ni < 16; ni++)
#pragma unroll
        for (int r = 0; r < 4; r++) oacc[ni][r] = 0.0f;

    const float scale = 0.08838834764831845f;
    const int nkv = (q0 + 64) / 32;

    auto load_kv = [&](int kt) {
        const uint32_t dstb = smb + (uint32_t)((kt & 1) * 2 * KV_TILE_F * 4);
        const float* ksrc = Kg + (size_t)kt * 4096;
        const float* vsrc = Vg + (size_t)kt * 4096;
#pragma unroll
        for (int i = 0; i < 8; i++) {
            int c = tid + i * 128;
            int sub = c >> 4, q = c & 15;
            uint32_t off = (uint32_t)((sub * 68 + q * 4) * 4);
            CP_ASYNC16(dstb + off, ksrc + c * 4);
            CP_ASYNC16(dstb + KV_TILE_F * 4 + off, vsrc + c * 4);
        }
        CP_COMMIT();
    };

    load_kv(0);

    for (int kt = 0; kt < nkv; kt++) {
        const int kv0 = kt * 32;
        asm volatile("cp.async.wait_group 0;" ::: "memory");
        __syncthreads();
        if (kt + 1 < nkv) load_kv(kt + 1);

        const float* Ks = sm + (kt & 1) * 2 * KV_TILE_F;
        const float* Vs = Ks + KV_TILE_F;

        float sacc[4][4];
#pragma unroll
        for (int ni = 0; ni < 4; ni++)
#pragma unroll
            for (int r = 0; r < 4; r++) sacc[ni][r] = 0.0f;

#pragma unroll
        for (int dk = 0; dk < 16; dk++) {
#pragma unroll
            for (int ni = 0; ni < 4; ni++) {
                float bfr[2];
                *(float2*)bfr = *(float2*)&Ks[(ni * 16 + dk) * 68 + lane * 2];
                mma_tf32(sacc[ni], qfr[dk], bfr);
            }
        }

        const bool needMask = (kt >= 2 * qb);
#pragma unroll
        for (int ni = 0; ni < 4; ni++) {
            int c0 = kv0 + ni * 8 + 2 * lk;
#pragma unroll
            for (int r = 0; r < 4; r++) sacc[ni][r] *= scale;
            if (needMask) {
                if (c0     > row0g) sacc[ni][0] = -1e30f;
                if (c0 + 1 > row0g) sacc[ni][1] = -1e30f;
                if (c0     > row1g) sacc[ni][2] = -1e30f;
                if (c0 + 1 > row1g) sacc[ni][3] = -1e30f;
            }
        }

        float rmax0 = -1e30f, rmax1 = -1e30f;
#pragma unroll
        for (int ni = 0; ni < 4; ni++) {
            rmax0 = fmaxf(rmax0, fmaxf(sacc[ni][0], sacc[ni][1]));
            rmax1 = fmaxf(rmax1, fmaxf(sacc[ni][2], sacc[ni][3]));
        }
        rmax0 = fmaxf(rmax0, __shfl_xor_sync(0xffffffffu, rmax0, 1));
        rmax0 = fmaxf(rmax0, __shfl_xor_sync(0xffffffffu, rmax0, 2));
        rmax1 = fmaxf(rmax1, __shfl_xor_sync(0xffffffffu, rmax1, 1));
        rmax1 = fmaxf(rmax1, __shfl_xor_sync(0xffffffffu, rmax1, 2));
        float mn0 = fmaxf(m0, rmax0);
        float mn1 = fmaxf(m1, rmax1);
        float al0 = __expf(m0 - mn0);
        float al1 = __expf(m1 - mn1);
        float rs0 = 0.0f, rs1 = 0.0f;
#pragma unroll
        for (int ni = 0; ni < 4; ni++) {
            sacc[ni][0] = __expf(sacc[ni][0] - mn0);
            sacc[ni][1] = __expf(sacc[ni][1] - mn0);
            sacc[ni][2] = __expf(sacc[ni][2] - mn1);
            sacc[ni][3] = __expf(sacc[ni][3] - mn1);
            rs0 += sacc[ni][0] + sacc[ni][1];
            rs1 += sacc[ni][2] + sacc[ni][3];
        }
        rs0 += __shfl_xor_sync(0xffffffffu, rs0, 1);
        rs0 += __shfl_xor_sync(0xffffffffu, rs0, 2);
        rs1 += __shfl_xor_sync(0xffffffffu, rs1, 1);
        rs1 += __shfl_xor_sync(0xffffffffu, rs1, 2);
        l0 = l0 * al0 + rs0;
        l1 = l1 * al1 + rs1;
        m0 = mn0;
        m1 = mn1;
#pragma unroll
        for (int ni = 0; ni < 16; ni++) {
            oacc[ni][0] *= al0; oacc[ni][1] *= al0;
            oacc[ni][2] *= al1; oacc[ni][3] *= al1;
        }

        // ---- O += P @ V ; P A-frags gathered via intra-quad shuffles ----
        // P(row lm, col kt2*8+j) lives in lane lm*4+(j>>1), reg sacc[kt2][j&1]
        // (rows lm+8 in regs [2],[3]).  afr = to_tf32(select) — bit-identical
        // to the old smem round-trip.
        const int src0 = lm * 4 + (lk >> 1);
        const bool odd = (lk & 1) != 0;
#pragma unroll
        for (int kt2 = 0; kt2 < 4; kt2++) {
            float e00 = __shfl_sync(0xffffffffu, sacc[kt2][0], src0);
            float e10 = __shfl_sync(0xffffffffu, sacc[kt2][1], src0);
            float e20 = __shfl_sync(0xffffffffu, sacc[kt2][2], src0);
            float e30 = __shfl_sync(0xffffffffu, sacc[kt2][3], src0);
            float e01 = __shfl_sync(0xffffffffu, sacc[kt2][0], src0 + 2);
            float e11 = __shfl_sync(0xffffffffu, sacc[kt2][1], src0 + 2);
            float e21 = __shfl_sync(0xffffffffu, sacc[kt2][2], src0 + 2);
            float e31 = __shfl_sync(0xffffffffu, sacc[kt2][3], src0 + 2);
            float afr[4];
            afr[0] = to_tf32(odd ? e10 : e00);
            afr[1] = to_tf32(odd ? e30 : e20);
            afr[2] = to_tf32(odd ? e11 : e01);
            afr[3] = to_tf32(odd ? e31 : e21);
#pragma unroll
            for (int ni = 0; ni < 16; ni++) {
                float bfr[2];
                *(float2*)bfr = *(float2*)&Vs[(kt2 * 16 + ni) * 68 + lane * 2];
                mma_tf32(oacc[ni], afr, bfr);
            }
        }
    }

    float inv0 = 1.0f / l0;
    float inv1 = 1.0f / l1;
    const size_t rowg = (size_t)b * T_ + (size_t)row0g;
    const size_t pglob = (rowg >> 4) * 8 + (rowg & 7);
#pragma unroll
    for (int ni = 0; ni < 16; ni++) {
        int col = h * D_ + ni * 8 + 2 * lk;
        float4 v;
        v.x = to_tf32(oacc[ni][0] * inv0);
        v.y = to_tf32(oacc[ni][2] * inv1);
        v.z = to_tf32(oacc[ni][1] * inv0);
        v.w = to_tf32(oacc[ni][3] * inv1);
        *(float4*)&g_attn[(pglob * C_ + col) * 2] = v;
    }
}

// ---------------- launch -------------------------------------------------------
extern "C" void kernel_launch(void* const* d_in, const int* in_sizes, int n_in,
                              void* d_out, int out_size)
{
    const float* x      = (const float*)d_in[0];
    const float* cosg   = (const float*)d_in[1];
    const float* sing   = (const float*)d_in[2];
    const float* W_qkv  = (const float*)d_in[3];
    const float* W_proj = (const float*)d_in[4];
    float* out = (float*)d_out;

    float* Qb;     cudaGetSymbolAddress((void**)&Qb,     g_Q);
    float* Kb;     cudaGetSymbolAddress((void**)&Kb,     g_K);
    float* Vb;     cudaGetSymbolAddress((void**)&Vb,     g_V);
    float* attn;   cudaGetSymbolAddress((void**)&attn,   g_attn);
    float* xc;     cudaGetSymbolAddress((void**)&xc,     g_xc);
    float* wqkvC;  cudaGetSymbolAddress((void**)&wqkvC,  g_wqkvC);
    float* wprojC; cudaGetSymbolAddress((void**)&wprojC, g_wprojC);

    const int M = B_ * T_;   // 4096

    cudaFuncSetAttribute(gemm_v6_kernel,
                         cudaFuncAttributeMaxDynamicSharedMemorySize, V5_SMEM_BYTES);
    cudaFuncSetAttribute(attn_mma_kernel,
                         cudaFuncAttributeMaxDynamicSharedMemorySize,
                         ATTN_SMEM_FLOATS * sizeof(float));

    // 0) pack + tf32-round operands
    {
        int na = (M * C_) / 4;
        pack_a_kernel<<<(na + 255) / 256, 256>>>(x, xc, C_, na);
        int nbq = (C_ * 3 * C_) / 4;
        pack_b_kernel<<<(nbq + 255) / 256, 256>>>(W_qkv, wqkvC, 3 * C_, nbq);
        int nbp = (C_ * C_) / 4;
        pack_b_kernel<<<(nbp + 255) / 256, 256>>>(W_proj, wprojC, C_, nbp);
    }

    // 1) qkv GEMM with fused RoPE/pack epilogue -> g_Q / g_K / g_V
    {
        dim3 grid(3 * C_ / V5_BN, M / V5_BM);   // (48, 32)
        gemm_v6_kernel<<<grid, 256, V5_SMEM_BYTES>>>(
            xc, wqkvC, nullptr, cosg, sing, Qb, Kb, Vb, M, 3 * C_, C_, 1);
    }
    // 2) attention -> g_attn (packed-A), LPT order, shuffle P-transpose
    {
        dim3 grid(T_ / 64, B_ * H_);            // (32, 32)
        attn_mma_kernel<<<grid, 128, ATTN_SMEM_FLOATS * sizeof(float)>>>(Qb, Kb, Vb);
    }
    // 3) out = attn @ W_proj (plain epilogue)
    {
        dim3 grid(C_ / V5_BN, M / V5_BM);       // (16, 32)
        gemm_v6_kernel<<<grid, 256, V5_SMEM_BYTES>>>(
            attn, wprojC, out, nullptr, nullptr, nullptr, nullptr, nullptr,
            M, C_, C_, 0);
    }
}

// round 16
// speedup vs baseline: 1.1953x; 1.1556x over previous
#include <cuda_runtime.h>
#include <cstdio>
#include <cstdint>

#define B_ 2
#define T_ 2048
#define C_ 2048
#define H_ 16
#define D_ 128

// ---------------- scratch (device globals: no runtime allocation) ----------------
__device__ float g_Q[(size_t)B_ * H_ * T_ * D_];
__device__ float g_K[(size_t)B_ * H_ * T_ * D_];      // PACKED B-frag tiles
__device__ float g_V[(size_t)B_ * H_ * T_ * D_];      // PACKED B-frag tiles
__device__ float g_attn[(size_t)B_ * T_ * C_];        // PACKED-A layout
__device__ float g_xc[(size_t)B_ * T_ * C_];          // packed-A tf32 x
__device__ float g_wqkvC[(size_t)C_ * 3 * C_];        // packed-B tf32 W_qkv
__device__ float g_wprojC[(size_t)C_ * C_];           // packed-B tf32 W_proj

// ---------------- helpers -------------------------------------------------------
__device__ __forceinline__ float to_tf32(float x) {
    unsigned u;
    asm("cvt.rna.tf32.f32 %0, %1;" : "=r"(u) : "f"(x));
    return __uint_as_float(u);
}

__device__ __forceinline__ void mma_tf32(float c[4], const float a[4], const float b[2]) {
    asm volatile(
        "mma.sync.aligned.m16n8k8.row.col.f32.tf32.tf32.f32 "
        "{%0,%1,%2,%3}, {%4,%5,%6,%7}, {%8,%9}, {%0,%1,%2,%3};"
        : "+f"(c[0]), "+f"(c[1]), "+f"(c[2]), "+f"(c[3])
        : "r"(__float_as_uint(a[0])), "r"(__float_as_uint(a[1])),
          "r"(__float_as_uint(a[2])), "r"(__float_as_uint(a[3])),
          "r"(__float_as_uint(b[0])), "r"(__float_as_uint(b[1])));
}

__device__ __forceinline__ uint32_t smem_u32(const void* p) {
    uint32_t a;
    asm("{ .reg .u64 t; cvta.to.shared.u64 t, %1; cvt.u32.u64 %0, t; }" : "=r"(a) : "l"(p));
    return a;
}

#define CP_ASYNC16(dst, src) \
    asm volatile("cp.async.cg.shared.global [%0], [%1], 16;" :: "r"(dst), "l"(src) : "memory")
#define CP_COMMIT() asm volatile("cp.async.commit_group;" ::: "memory")

// ============ GEMM v6: packed operands + optional fused RoPE/pack epilogue ======
#define V5_BM 128
#define V5_BN 128
#define V5_BK 32
#define V5_ASTR 72
#define V5_BSTR 264
#define V5_AFLOATS (64 * V5_ASTR)             // 4608
#define V5_BFLOATS (16 * V5_BSTR)             // 4224
#define V5_STAGEF (V5_AFLOATS + V5_BFLOATS)   // 8832 floats
#define V5_NST 3
#define V5_SMEM_BYTES (V5_NST * V5_STAGEF * 4)  // 105984

// mode 0: plain row-major C write (proj).  mode 1: fused qkv epilogue.
__global__ __launch_bounds__(256, 2) void gemm_v6_kernel(
    const float* __restrict__ Ap, const float* __restrict__ Bp, float* __restrict__ Cm,
    const float* __restrict__ cosg, const float* __restrict__ sing,
    float* __restrict__ Qout, float* __restrict__ Kout, float* __restrict__ Vout,
    int M, int N, int K, int mode, int m_base)
{
    extern __shared__ float sm[];

    const int tid = threadIdx.x;
    const int warp = tid >> 5;
    const int lane = tid & 31;
    const int lm = lane >> 2;
    const int lk = lane & 3;

    const int m0 = m_base + blockIdx.y * V5_BM;
    const int n0 = blockIdx.x * V5_BN;
    const int wm = (warp >> 2) * 64;
    const int wn = (warp & 3) * 32;

    const uint32_t smb = smem_u32(sm);

    float acc[4][4][4];
#pragma unroll
    for (int mi = 0; mi < 4; mi++)
#pragma unroll
        for (int ni = 0; ni < 4; ni++)
#pragma unroll
            for (int r = 0; r < 4; r++) acc[mi][ni][r] = 0.0f;

    auto load_stage = [&](int s) {
        const int k0 = s * V5_BK;
        const uint32_t base = smb + (uint32_t)((s % V5_NST) * V5_STAGEF * 4);
#pragma unroll
        for (int i = 0; i < 4; i++) {
            int id = tid + i * 256;
            int p = id >> 4, kc = id & 15;
            uint32_t dst = base + (uint32_t)((p * V5_ASTR + kc * 4) * 4);
            const float* src = Ap + ((size_t)(m0 / 2 + p) * K + k0 + kc * 2) * 2;
            CP_ASYNC16(dst, src);
        }
        const uint32_t bbase = base + V5_AFLOATS * 4;
#pragma unroll
        for (int i = 0; i < 4; i++) {
            int id = tid + i * 256;
            int kp = id >> 6, nc = id & 63;
            uint32_t dst = bbase + (uint32_t)((kp * V5_BSTR + nc * 4) * 4);
            const float* src = Bp + ((size_t)(k0 / 2 + kp) * N + n0 + nc * 2) * 2;
            CP_ASYNC16(dst, src);
        }
        CP_COMMIT();
    };

    const int nst = K / V5_BK;   // 64
    load_stage(0);
    load_stage(1);

    for (int ks = 0; ks < nst; ks++) {
        asm volatile("cp.async.wait_group %0;" :: "n"(1) : "memory");
        __syncthreads();

        const float* As = sm + (size_t)(ks % V5_NST) * V5_STAGEF;
        const float* Bs = As + V5_AFLOATS;

#pragma unroll
        for (int kk = 0; kk < V5_BK; kk += 8) {
            float afr[4][4];
#pragma unroll
            for (int mi = 0; mi < 4; mi++) {
                int aw = (((wm >> 4) + mi) * 8 + lm) * V5_ASTR + (kk + lk) * 2;
                *(float2*)&afr[mi][0] = *(const float2*)&As[aw];
                *(float2*)&afr[mi][2] = *(const float2*)&As[aw + 8];
            }
            float bfr[4][2];
#pragma unroll
            for (int ni = 0; ni < 4; ni++) {
                int bw = ((kk >> 3) * 4 + lk) * V5_BSTR + (wn + ni * 8 + lm) * 2;
                *(float2*)&bfr[ni][0] = *(const float2*)&Bs[bw];
            }
#pragma unroll
            for (int mi = 0; mi < 4; mi++)
#pragma unroll
                for (int ni = 0; ni < 4; ni++)
                    mma_tf32(acc[mi][ni], afr[mi], bfr[ni]);
        }

        if (ks + 2 < nst) load_stage(ks + 2);
        else CP_COMMIT();
    }

    if (mode == 0) {
#pragma unroll
        for (int mi = 0; mi < 4; mi++) {
#pragma unroll
            for (int ni = 0; ni < 4; ni++) {
                int gr = m0 + wm + mi * 16 + lm;
                int gc = n0 + wn + ni * 8 + lk * 2;
                float* p0 = Cm + (size_t)gr * N + gc;
                float* p1 = Cm + (size_t)(gr + 8) * N + gc;
                *(float2*)p0 = make_float2(acc[mi][ni][0], acc[mi][ni][1]);
                *(float2*)p1 = make_float2(acc[mi][ni][2], acc[mi][ni][3]);
            }
        }
        return;
    }

    // ---- fused qkv epilogue ----
    float* Ct = sm;                    // [128][132]
    float* stP = sm + 128 * 132;       // 4096 floats
    __syncthreads();
#pragma unroll
    for (int mi = 0; mi < 4; mi++) {
#pragma unroll
        for (int ni = 0; ni < 4; ni++) {
            int rr = wm + mi * 16 + lm;
            int cc = wn + ni * 8 + lk * 2;
            *(float2*)&Ct[rr * 132 + cc] = make_float2(acc[mi][ni][0], acc[mi][ni][1]);
            *(float2*)&Ct[(rr + 8) * 132 + cc] = make_float2(acc[mi][ni][2], acc[mi][ni][3]);
        }
    }
    __syncthreads();

    const int type = n0 >> 11;           // 0:Q 1:K 2:V
    const int h = (n0 & 2047) >> 7;
    const int b = m0 >> 11;
    const int t0 = m0 & 2047;
    const size_t bh = (size_t)(b * H_ + h);

    if (type == 0) {
#pragma unroll
        for (int i = 0; i < 32; i++) {
            int idx = tid + i * 256;
            int r = idx >> 6, d = idx & 63;
            int t = t0 + r;
            float c = cosg[t * 64 + d];
            float s = sing[t * 64 + d];
            float q1 = Ct[r * 132 + d];
            float q2 = Ct[r * 132 + d + 64];
            float* Qrow = Qout + (bh * T_ + t) * D_;
            Qrow[d]      = q1 * c - q2 * s;
            Qrow[d + 64] = q1 * s + q2 * c;
        }
    } else if (type == 1) {
        for (int st = 0; st < 4; st++) {
#pragma unroll
            for (int i = 0; i < 8; i++) {
                int idx = tid + i * 256;
                int r = idx >> 6, d = idx & 63;
                int t = t0 + st * 32 + r;
                float c = cosg[t * 64 + d];
                float s = sing[t * 64 + d];
                float k1 = Ct[(st * 32 + r) * 132 + d];
                float k2 = Ct[(st * 32 + r) * 132 + d + 64];
                float kr1 = to_tf32(k1 * c - k2 * s);
                float kr2 = to_tf32(k1 * s + k2 * c);
                stP[((r >> 3) * 16 + (d >> 3)) * 64 + ((r & 7) * 4 + (d & 3)) * 2 + ((d >> 2) & 1)] = kr1;
                int d2 = d + 64;
                stP[((r >> 3) * 16 + (d2 >> 3)) * 64 + ((r & 7) * 4 + (d2 & 3)) * 2 + ((d2 >> 2) & 1)] = kr2;
            }
            __syncthreads();
            float* kout = Kout + bh * ((size_t)T_ * D_) + (size_t)(t0 / 32 + st) * 4096;
#pragma unroll
            for (int i = 0; i < 4; i++) {
                int c2 = tid + i * 256;
                *(float4*)(kout + c2 * 4) = *(const float4*)(stP + c2 * 4);
            }
            __syncthreads();
        }
    } else {
        for (int st = 0; st < 4; st++) {
#pragma unroll
            for (int i = 0; i < 16; i++) {
                int idx = tid + i * 256;
                int r = idx >> 7, d = idx & 127;
                float v = to_tf32(Ct[(st * 32 + r) * 132 + d]);
                stP[((r >> 3) * 16 + (d >> 3)) * 64 + ((d & 7) * 4 + (r & 3)) * 2 + ((r >> 2) & 1)] = v;
            }
            __syncthreads();
            float* vout = Vout + bh * ((size_t)T_ * D_) + (size_t)(t0 / 32 + st) * 4096;
#pragma unroll
            for (int i = 0; i < 4; i++) {
                int c2 = tid + i * 256;
                *(float4*)(vout + c2 * 4) = *(const float4*)(stP + c2 * 4);
            }
            __syncthreads();
        }
    }
}

// ---------------- pack pre-passes (tf32-round + layout) -------------------------
__global__ __launch_bounds__(256) void pack_a_kernel(
    const float* __restrict__ src, float* __restrict__ dst, int K, int nchunk)
{
    int c = blockIdx.x * blockDim.x + threadIdx.x;
    if (c >= nchunk) return;
    int kh = K >> 1;
    int p = c / kh, kc = c - p * kh;
    int m = (p >> 3) * 16 + (p & 7);
    int k = kc * 2;
    const float* r0 = src + (size_t)m * K + k;
    const float* r1 = r0 + (size_t)8 * K;
    float4 v;
    v.x = to_tf32(r0[0]); v.y = to_tf32(r1[0]);
    v.z = to_tf32(r0[1]); v.w = to_tf32(r1[1]);
    *(float4*)(dst + (size_t)c * 4) = v;
}

__global__ __launch_bounds__(256) void pack_b_kernel(
    const float* __restrict__ src, float* __restrict__ dst, int N, int nchunk)
{
    int c = blockIdx.x * blockDim.x + threadIdx.x;
    if (c >= nchunk) return;
    int nh = N >> 1;
    int kp = c / nh, nc = c - kp * nh;
    int k = (kp >> 2) * 8 + (kp & 3);
    int n = nc * 2;
    const float* r0 = src + (size_t)k * N + n;
    const float* r1 = r0 + (size_t)4 * N;
    float4 v;
    v.x = to_tf32(r0[0]); v.y = to_tf32(r1[0]);
    v.z = to_tf32(r0[1]); v.w = to_tf32(r1[1]);
    *(float4*)(dst + (size_t)c * 4) = v;
}

// ---------------- attention v4: shuffle P-transpose (no Ps smem) ----------------
#define KV_TILE_F (64 * 68)
#define ATTN_SMEM_FLOATS (2 * 2 * KV_TILE_F)   // 69632 B

__global__ __launch_bounds__(128, 2) void attn_mma_kernel(
    const float* __restrict__ Q, const float* __restrict__ Kp,
    const float* __restrict__ Vp, int bh_base)
{
    extern __shared__ float sm[];

    const int qb = (int)gridDim.x - 1 - (int)blockIdx.x;   // LPT
    const int bh = bh_base + blockIdx.y;
    const int b = bh >> 4;
    const int h = bh & 15;
    const int tid = threadIdx.x;
    const int w = tid >> 5;
    const int lane = tid & 31;
    const int lm = lane >> 2;
    const int lk = lane & 3;
    const int q0 = qb * 64;

    const float* Qg = Q + ((size_t)bh * T_ + q0) * D_;
    const float* Kg = Kp + (size_t)bh * T_ * D_;
    const float* Vg = Vp + (size_t)bh * T_ * D_;
    const uint32_t smb = smem_u32(sm);

    const int row0g = q0 + w * 16 + lm;
    const int row1g = row0g + 8;

    float qfr[16][4];
    {
        const float* q0p = Qg + (size_t)(w * 16 + lm) * D_;
        const float* q1p = q0p + 8 * D_;
#pragma unroll
        for (int dk = 0; dk < 16; dk++) {
            int col = dk * 8 + lk;
            qfr[dk][0] = to_tf32(q0p[col]);
            qfr[dk][1] = to_tf32(q1p[col]);
            qfr[dk][2] = to_tf32(q0p[col + 4]);
            qfr[dk][3] = to_tf32(q1p[col + 4]);
        }
    }

    float m0 = -1e30f, m1 = -1e30f, l0 = 0.0f, l1 = 0.0f;
    float oacc[16][4];
#pragma unroll
    for (int ni = 0; ni < 16; ni++)
#pragma unroll
        for (int r = 0; r < 4; r++) oacc[ni][r] = 0.0f;

    const float scale = 0.08838834764831845f;
    const int nkv = (q0 + 64) / 32;

    auto load_kv = [&](int kt) {
        const uint32_t dstb = smb + (uint32_t)((kt & 1) * 2 * KV_TILE_F * 4);
        const float* ksrc = Kg + (size_t)kt * 4096;
        const float* vsrc = Vg + (size_t)kt * 4096;
#pragma unroll
        for (int i = 0; i < 8; i++) {
            int c = tid + i * 128;
            int sub = c >> 4, q = c & 15;
            uint32_t off = (uint32_t)((sub * 68 + q * 4) * 4);
            CP_ASYNC16(dstb + off, ksrc + c * 4);
            CP_ASYNC16(dstb + KV_TILE_F * 4 + off, vsrc + c * 4);
        }
        CP_COMMIT();
    };

    load_kv(0);

    for (int kt = 0; kt < nkv; kt++) {
        const int kv0 = kt * 32;
        asm volatile("cp.async.wait_group 0;" ::: "memory");
        __syncthreads();
        if (kt + 1 < nkv) load_kv(kt + 1);

        const float* Ks = sm + (kt & 1) * 2 * KV_TILE_F;
        const float* Vs = Ks + KV_TILE_F;

        float sacc[4][4];
#pragma unroll
        for (int ni = 0; ni < 4; ni++)
#pragma unroll
            for (int r = 0; r < 4; r++) sacc[ni][r] = 0.0f;

#pragma unroll
        for (int dk = 0; dk < 16; dk++) {
#pragma unroll
            for (int ni = 0; ni < 4; ni++) {
                float bfr[2];
                *(float2*)bfr = *(float2*)&Ks[(ni * 16 + dk) * 68 + lane * 2];
                mma_tf32(sacc[ni], qfr[dk], bfr);
            }
        }

        const bool needMask = (kt >= 2 * qb);
#pragma unroll
        for (int ni = 0; ni < 4; ni++) {
            int c0 = kv0 + ni * 8 + 2 * lk;
#pragma unroll
            for (int r = 0; r < 4; r++) sacc[ni][r] *= scale;
            if (needMask) {
                if (c0     > row0g) sacc[ni][0] = -1e30f;
                if (c0 + 1 > row0g) sacc[ni][1] = -1e30f;
                if (c0     > row1g) sacc[ni][2] = -1e30f;
                if (c0 + 1 > row1g) sacc[ni][3] = -1e30f;
            }
        }

        float rmax0 = -1e30f, rmax1 = -1e30f;
#pragma unroll
        for (int ni = 0; ni < 4; ni++) {
            rmax0 = fmaxf(rmax0, fmaxf(sacc[ni][0], sacc[ni][1]));
            rmax1 = fmaxf(rmax1, fmaxf(sacc[ni][2], sacc[ni][3]));
        }
        rmax0 = fmaxf(rmax0, __shfl_xor_sync(0xffffffffu, rmax0, 1));
        rmax0 = fmaxf(rmax0, __shfl_xor_sync(0xffffffffu, rmax0, 2));
        rmax1 = fmaxf(rmax1, __shfl_xor_sync(0xffffffffu, rmax1, 1));
        rmax1 = fmaxf(rmax1, __shfl_xor_sync(0xffffffffu, rmax1, 2));
        float mn0 = fmaxf(m0, rmax0);
        float mn1 = fmaxf(m1, rmax1);
        float al0 = __expf(m0 - mn0);
        float al1 = __expf(m1 - mn1);
        float rs0 = 0.0f, rs1 = 0.0f;
#pragma unroll
        for (int ni = 0; ni < 4; ni++) {
            sacc[ni][0] = __expf(sacc[ni][0] - mn0);
            sacc[ni][1] = __expf(sacc[ni][1] - mn0);
            sacc[ni][2] = __expf(sacc[ni][2] - mn1);
            sacc[ni][3] = __expf(sacc[ni][3] - mn1);
            rs0 += sacc[ni][0] + sacc[ni][1];
            rs1 += sacc[ni][2] + sacc[ni][3];
        }
        rs0 += __shfl_xor_sync(0xffffffffu, rs0, 1);
        rs0 += __shfl_xor_sync(0xffffffffu, rs0, 2);
        rs1 += __shfl_xor_sync(0xffffffffu, rs1, 1);
        rs1 += __shfl_xor_sync(0xffffffffu, rs1, 2);
        l0 = l0 * al0 + rs0;
        l1 = l1 * al1 + rs1;
        m0 = mn0;
        m1 = mn1;
#pragma unroll
        for (int ni = 0; ni < 16; ni++) {
            oacc[ni][0] *= al0; oacc[ni][1] *= al0;
            oacc[ni][2] *= al1; oacc[ni][3] *= al1;
        }

        const int src0 = lm * 4 + (lk >> 1);
        const bool odd = (lk & 1) != 0;
#pragma unroll
        for (int kt2 = 0; kt2 < 4; kt2++) {
            float e00 = __shfl_sync(0xffffffffu, sacc[kt2][0], src0);
            float e10 = __shfl_sync(0xffffffffu, sacc[kt2][1], src0);
            float e20 = __shfl_sync(0xffffffffu, sacc[kt2][2], src0);
            float e30 = __shfl_sync(0xffffffffu, sacc[kt2][3], src0);
            float e01 = __shfl_sync(0xffffffffu, sacc[kt2][0], src0 + 2);
            float e11 = __shfl_sync(0xffffffffu, sacc[kt2][1], src0 + 2);
            float e21 = __shfl_sync(0xffffffffu, sacc[kt2][2], src0 + 2);
            float e31 = __shfl_sync(0xffffffffu, sacc[kt2][3], src0 + 2);
            float afr[4];
            afr[0] = to_tf32(odd ? e10 : e00);
            afr[1] = to_tf32(odd ? e30 : e20);
            afr[2] = to_tf32(odd ? e11 : e01);
            afr[3] = to_tf32(odd ? e31 : e21);
#pragma unroll
            for (int ni = 0; ni < 16; ni++) {
                float bfr[2];
                *(float2*)bfr = *(float2*)&Vs[(kt2 * 16 + ni) * 68 + lane * 2];
                mma_tf32(oacc[ni], afr, bfr);
            }
        }
    }

    float inv0 = 1.0f / l0;
    float inv1 = 1.0f / l1;
    const size_t rowg = (size_t)b * T_ + (size_t)row0g;
    const size_t pglob = (rowg >> 4) * 8 + (rowg & 7);
#pragma unroll
    for (int ni = 0; ni < 16; ni++) {
        int col = h * D_ + ni * 8 + 2 * lk;
        float4 v;
        v.x = to_tf32(oacc[ni][0] * inv0);
        v.y = to_tf32(oacc[ni][2] * inv1);
        v.z = to_tf32(oacc[ni][1] * inv0);
        v.w = to_tf32(oacc[ni][3] * inv1);
        *(float4*)&g_attn[(pglob * C_ + col) * 2] = v;
    }
}

// ---------------- launch: split-batch dual-stream pipeline ----------------------
extern "C" void kernel_launch(void* const* d_in, const int* in_sizes, int n_in,
                              void* d_out, int out_size)
{
    const float* x      = (const float*)d_in[0];
    const float* cosg   = (const float*)d_in[1];
    const float* sing   = (const float*)d_in[2];
    const float* W_qkv  = (const float*)d_in[3];
    const float* W_proj = (const float*)d_in[4];
    float* out = (float*)d_out;

    float* Qb;     cudaGetSymbolAddress((void**)&Qb,     g_Q);
    float* Kb;     cudaGetSymbolAddress((void**)&Kb,     g_K);
    float* Vb;     cudaGetSymbolAddress((void**)&Vb,     g_V);
    float* attn;   cudaGetSymbolAddress((void**)&attn,   g_attn);
    float* xc;     cudaGetSymbolAddress((void**)&xc,     g_xc);
    float* wqkvC;  cudaGetSymbolAddress((void**)&wqkvC,  g_wqkvC);
    float* wprojC; cudaGetSymbolAddress((void**)&wprojC, g_wprojC);

    const int M = B_ * T_;   // 4096

    static cudaStream_t s2 = nullptr;
    static cudaEvent_t evFork = nullptr, evJoin = nullptr;
    if (s2 == nullptr) {
        cudaStreamCreateWithFlags(&s2, cudaStreamNonBlocking);
        cudaEventCreateWithFlags(&evFork, cudaEventDisableTiming);
        cudaEventCreateWithFlags(&evJoin, cudaEventDisableTiming);
    }

    cudaFuncSetAttribute(gemm_v6_kernel,
                         cudaFuncAttributeMaxDynamicSharedMemorySize, V5_SMEM_BYTES);
    cudaFuncSetAttribute(attn_mma_kernel,
                         cudaFuncAttributeMaxDynamicSharedMemorySize,
                         ATTN_SMEM_FLOATS * sizeof(float));

    // 0) pack + tf32-round operands (main stream)
    {
        int na = (M * C_) / 4;
        pack_a_kernel<<<(na + 255) / 256, 256>>>(x, xc, C_, na);
        int nbq = (C_ * 3 * C_) / 4;
        pack_b_kernel<<<(nbq + 255) / 256, 256>>>(W_qkv, wqkvC, 3 * C_, nbq);
        int nbp = (C_ * C_) / 4;
        pack_b_kernel<<<(nbp + 255) / 256, 256>>>(W_proj, wprojC, C_, nbp);
    }

    // fork: s2 joins after packs
    cudaEventRecord(evFork, 0);
    cudaStreamWaitEvent(s2, evFork, 0);

    const dim3 gQKV(3 * C_ / V5_BN, 16);   // per-batch: (48, 16)
    const dim3 gATT(T_ / 64, 16);          // per-batch: (32, 16)
    const dim3 gPRJ(C_ / V5_BN, 16);       // per-batch: (16, 16)
    const size_t aSm = ATTN_SMEM_FLOATS * sizeof(float);

    // batch 0 on main stream
    gemm_v6_kernel<<<gQKV, 256, V5_SMEM_BYTES>>>(
        xc, wqkvC, nullptr, cosg, sing, Qb, Kb, Vb, M, 3 * C_, C_, 1, 0);
    attn_mma_kernel<<<gATT, 128, aSm>>>(Qb, Kb, Vb, 0);
    gemm_v6_kernel<<<gPRJ, 256, V5_SMEM_BYTES>>>(
        attn, wprojC, out, nullptr, nullptr, nullptr, nullptr, nullptr,
        M, C_, C_, 0, 0);

    // batch 1 on s2
    gemm_v6_kernel<<<gQKV, 256, V5_SMEM_BYTES, s2>>>(
        xc, wqkvC, nullptr, cosg, sing, Qb, Kb, Vb, M, 3 * C_, C_, 1, 2048);
    attn_mma_kernel<<<gATT, 128, aSm, s2>>>(Qb, Kb, Vb, 16);
    gemm_v6_kernel<<<gPRJ, 256, V5_SMEM_BYTES, s2>>>(
        attn, wprojC, out, nullptr, nullptr, nullptr, nullptr, nullptr,
        M, C_, C_, 0, 2048);

    // join
    cudaEventRecord(evJoin, s2);
    cudaStreamWaitEvent(0, evJoin, 0);
}

// round 17
// speedup vs baseline: 1.1974x; 1.0018x over previous
#include <cuda_runtime.h>
#include <cstdio>
#include <cstdint>

#define B_ 2
#define T_ 2048
#define C_ 2048
#define H_ 16
#define D_ 128

// ---------------- scratch (device globals: no runtime allocation) ----------------
__device__ float g_Q[(size_t)B_ * H_ * T_ * D_];
__device__ float g_K[(size_t)B_ * H_ * T_ * D_];      // PACKED B-frag tiles
__device__ float g_V[(size_t)B_ * H_ * T_ * D_];      // PACKED B-frag tiles
__device__ float g_attn[(size_t)B_ * T_ * C_];        // PACKED-A layout
__device__ float g_xc[(size_t)B_ * T_ * C_];          // packed-A tf32 x
__device__ float g_wqkvC[(size_t)C_ * 3 * C_];        // packed-B tf32 W_qkv
__device__ float g_wprojC[(size_t)C_ * C_];           // packed-B tf32 W_proj

// ---------------- helpers -------------------------------------------------------
__device__ __forceinline__ float to_tf32(float x) {
    unsigned u;
    asm("cvt.rna.tf32.f32 %0, %1;" : "=r"(u) : "f"(x));
    return __uint_as_float(u);
}

__device__ __forceinline__ void mma_tf32(float c[4], const float a[4], const float b[2]) {
    asm volatile(
        "mma.sync.aligned.m16n8k8.row.col.f32.tf32.tf32.f32 "
        "{%0,%1,%2,%3}, {%4,%5,%6,%7}, {%8,%9}, {%0,%1,%2,%3};"
        : "+f"(c[0]), "+f"(c[1]), "+f"(c[2]), "+f"(c[3])
        : "r"(__float_as_uint(a[0])), "r"(__float_as_uint(a[1])),
          "r"(__float_as_uint(a[2])), "r"(__float_as_uint(a[3])),
          "r"(__float_as_uint(b[0])), "r"(__float_as_uint(b[1])));
}

__device__ __forceinline__ uint32_t smem_u32(const void* p) {
    uint32_t a;
    asm("{ .reg .u64 t; cvta.to.shared.u64 t, %1; cvt.u32.u64 %0, t; }" : "=r"(a) : "l"(p));
    return a;
}

#define CP_ASYNC16(dst, src) \
    asm volatile("cp.async.cg.shared.global [%0], [%1], 16;" :: "r"(dst), "l"(src) : "memory")
#define CP_COMMIT() asm volatile("cp.async.commit_group;" ::: "memory")

// ============ GEMM v6: packed operands + optional fused RoPE/pack epilogue ======
#define V5_BM 128
#define V5_BN 128
#define V5_BK 32
#define V5_ASTR 72
#define V5_BSTR 264
#define V5_AFLOATS (64 * V5_ASTR)             // 4608
#define V5_BFLOATS (16 * V5_BSTR)             // 4224
#define V5_STAGEF (V5_AFLOATS + V5_BFLOATS)   // 8832 floats
#define V5_NST 3
#define V5_SMEM_BYTES (V5_NST * V5_STAGEF * 4)  // 105984

// mode 0: plain row-major C write (proj).  mode 1: fused qkv epilogue.
__global__ __launch_bounds__(256, 2) void gemm_v6_kernel(
    const float* __restrict__ Ap, const float* __restrict__ Bp, float* __restrict__ Cm,
    const float* __restrict__ cosg, const float* __restrict__ sing,
    float* __restrict__ Qout, float* __restrict__ Kout, float* __restrict__ Vout,
    int M, int N, int K, int mode, int m_base)
{
    extern __shared__ float sm[];

    const int tid = threadIdx.x;
    const int warp = tid >> 5;
    const int lane = tid & 31;
    const int lm = lane >> 2;
    const int lk = lane & 3;

    const int m0 = m_base + blockIdx.y * V5_BM;
    const int n0 = blockIdx.x * V5_BN;
    const int wm = (warp >> 2) * 64;
    const int wn = (warp & 3) * 32;

    const uint32_t smb = smem_u32(sm);

    float acc[4][4][4];
#pragma unroll
    for (int mi = 0; mi < 4; mi++)
#pragma unroll
        for (int ni = 0; ni < 4; ni++)
#pragma unroll
            for (int r = 0; r < 4; r++) acc[mi][ni][r] = 0.0f;

    auto load_stage = [&](int s) {
        const int k0 = s * V5_BK;
        const uint32_t base = smb + (uint32_t)((s % V5_NST) * V5_STAGEF * 4);
#pragma unroll
        for (int i = 0; i < 4; i++) {
            int id = tid + i * 256;
            int p = id >> 4, kc = id & 15;
            uint32_t dst = base + (uint32_t)((p * V5_ASTR + kc * 4) * 4);
            const float* src = Ap + ((size_t)(m0 / 2 + p) * K + k0 + kc * 2) * 2;
            CP_ASYNC16(dst, src);
        }
        const uint32_t bbase = base + V5_AFLOATS * 4;
#pragma unroll
        for (int i = 0; i < 4; i++) {
            int id = tid + i * 256;
            int kp = id >> 6, nc = id & 63;
            uint32_t dst = bbase + (uint32_t)((kp * V5_BSTR + nc * 4) * 4);
            const float* src = Bp + ((size_t)(k0 / 2 + kp) * N + n0 + nc * 2) * 2;
            CP_ASYNC16(dst, src);
        }
        CP_COMMIT();
    };

    const int nst = K / V5_BK;   // 64
    load_stage(0);
    load_stage(1);

    for (int ks = 0; ks < nst; ks++) {
        asm volatile("cp.async.wait_group %0;" :: "n"(1) : "memory");
        __syncthreads();

        const float* As = sm + (size_t)(ks % V5_NST) * V5_STAGEF;
        const float* Bs = As + V5_AFLOATS;

#pragma unroll
        for (int kk = 0; kk < V5_BK; kk += 8) {
            float afr[4][4];
#pragma unroll
            for (int mi = 0; mi < 4; mi++) {
                int aw = (((wm >> 4) + mi) * 8 + lm) * V5_ASTR + (kk + lk) * 2;
                *(float2*)&afr[mi][0] = *(const float2*)&As[aw];
                *(float2*)&afr[mi][2] = *(const float2*)&As[aw + 8];
            }
            float bfr[4][2];
#pragma unroll
            for (int ni = 0; ni < 4; ni++) {
                int bw = ((kk >> 3) * 4 + lk) * V5_BSTR + (wn + ni * 8 + lm) * 2;
                *(float2*)&bfr[ni][0] = *(const float2*)&Bs[bw];
            }
#pragma unroll
            for (int mi = 0; mi < 4; mi++)
#pragma unroll
                for (int ni = 0; ni < 4; ni++)
                    mma_tf32(acc[mi][ni], afr[mi], bfr[ni]);
        }

        if (ks + 2 < nst) load_stage(ks + 2);
        else CP_COMMIT();
    }

    if (mode == 0) {
#pragma unroll
        for (int mi = 0; mi < 4; mi++) {
#pragma unroll
            for (int ni = 0; ni < 4; ni++) {
                int gr = m0 + wm + mi * 16 + lm;
                int gc = n0 + wn + ni * 8 + lk * 2;
                float* p0 = Cm + (size_t)gr * N + gc;
                float* p1 = Cm + (size_t)(gr + 8) * N + gc;
                *(float2*)p0 = make_float2(acc[mi][ni][0], acc[mi][ni][1]);
                *(float2*)p1 = make_float2(acc[mi][ni][2], acc[mi][ni][3]);
            }
        }
        return;
    }

    // ---- fused qkv epilogue ----
    float* Ct = sm;                    // [128][132]
    float* stP = sm + 128 * 132;       // 4096 floats
    __syncthreads();
#pragma unroll
    for (int mi = 0; mi < 4; mi++) {
#pragma unroll
        for (int ni = 0; ni < 4; ni++) {
            int rr = wm + mi * 16 + lm;
            int cc = wn + ni * 8 + lk * 2;
            *(float2*)&Ct[rr * 132 + cc] = make_float2(acc[mi][ni][0], acc[mi][ni][1]);
            *(float2*)&Ct[(rr + 8) * 132 + cc] = make_float2(acc[mi][ni][2], acc[mi][ni][3]);
        }
    }
    __syncthreads();

    const int type = n0 >> 11;           // 0:Q 1:K 2:V
    const int h = (n0 & 2047) >> 7;
    const int b = m0 >> 11;
    const int t0 = m0 & 2047;
    const size_t bh = (size_t)(b * H_ + h);

    if (type == 0) {
#pragma unroll
        for (int i = 0; i < 32; i++) {
            int idx = tid + i * 256;
            int r = idx >> 6, d = idx & 63;
            int t = t0 + r;
            float c = cosg[t * 64 + d];
            float s = sing[t * 64 + d];
            float q1 = Ct[r * 132 + d];
            float q2 = Ct[r * 132 + d + 64];
            float* Qrow = Qout + (bh * T_ + t) * D_;
            Qrow[d]      = q1 * c - q2 * s;
            Qrow[d + 64] = q1 * s + q2 * c;
        }
    } else if (type == 1) {
        for (int st = 0; st < 4; st++) {
#pragma unroll
            for (int i = 0; i < 8; i++) {
                int idx = tid + i * 256;
                int r = idx >> 6, d = idx & 63;
                int t = t0 + st * 32 + r;
                float c = cosg[t * 64 + d];
                float s = sing[t * 64 + d];
                float k1 = Ct[(st * 32 + r) * 132 + d];
                float k2 = Ct[(st * 32 + r) * 132 + d + 64];
                float kr1 = to_tf32(k1 * c - k2 * s);
                float kr2 = to_tf32(k1 * s + k2 * c);
                stP[((r >> 3) * 16 + (d >> 3)) * 64 + ((r & 7) * 4 + (d & 3)) * 2 + ((d >> 2) & 1)] = kr1;
                int d2 = d + 64;
                stP[((r >> 3) * 16 + (d2 >> 3)) * 64 + ((r & 7) * 4 + (d2 & 3)) * 2 + ((d2 >> 2) & 1)] = kr2;
            }
            __syncthreads();
            float* kout = Kout + bh * ((size_t)T_ * D_) + (size_t)(t0 / 32 + st) * 4096;
#pragma unroll
            for (int i = 0; i < 4; i++) {
                int c2 = tid + i * 256;
                *(float4*)(kout + c2 * 4) = *(const float4*)(stP + c2 * 4);
            }
            __syncthreads();
        }
    } else {
        for (int st = 0; st < 4; st++) {
#pragma unroll
            for (int i = 0; i < 16; i++) {
                int idx = tid + i * 256;
                int r = idx >> 7, d = idx & 127;
                float v = to_tf32(Ct[(st * 32 + r) * 132 + d]);
                stP[((r >> 3) * 16 + (d >> 3)) * 64 + ((d & 7) * 4 + (r & 3)) * 2 + ((r >> 2) & 1)] = v;
            }
            __syncthreads();
            float* vout = Vout + bh * ((size_t)T_ * D_) + (size_t)(t0 / 32 + st) * 4096;
#pragma unroll
            for (int i = 0; i < 4; i++) {
                int c2 = tid + i * 256;
                *(float4*)(vout + c2 * 4) = *(const float4*)(stP + c2 * 4);
            }
            __syncthreads();
        }
    }
}

// ---------------- pack pre-passes (tf32-round + layout) -------------------------
__global__ __launch_bounds__(256) void pack_a_kernel(
    const float* __restrict__ src, float* __restrict__ dst, int K, int nchunk)
{
    int c = blockIdx.x * blockDim.x + threadIdx.x;
    if (c >= nchunk) return;
    int kh = K >> 1;
    int p = c / kh, kc = c - p * kh;
    int m = (p >> 3) * 16 + (p & 7);
    int k = kc * 2;
    const float* r0 = src + (size_t)m * K + k;
    const float* r1 = r0 + (size_t)8 * K;
    float4 v;
    v.x = to_tf32(r0[0]); v.y = to_tf32(r1[0]);
    v.z = to_tf32(r0[1]); v.w = to_tf32(r1[1]);
    *(float4*)(dst + (size_t)c * 4) = v;
}

__global__ __launch_bounds__(256) void pack_b_kernel(
    const float* __restrict__ src, float* __restrict__ dst, int N, int nchunk)
{
    int c = blockIdx.x * blockDim.x + threadIdx.x;
    if (c >= nchunk) return;
    int nh = N >> 1;
    int kp = c / nh, nc = c - kp * nh;
    int k = (kp >> 2) * 8 + (kp & 3);
    int n = nc * 2;
    const float* r0 = src + (size_t)k * N + n;
    const float* r1 = r0 + (size_t)4 * N;
    float4 v;
    v.x = to_tf32(r0[0]); v.y = to_tf32(r1[0]);
    v.z = to_tf32(r0[1]); v.w = to_tf32(r1[1]);
    *(float4*)(dst + (size_t)c * 4) = v;
}

// ---------------- attention v4: shuffle P-transpose (no Ps smem) ----------------
#define KV_TILE_F (64 * 68)
#define ATTN_SMEM_FLOATS (2 * 2 * KV_TILE_F)   // 69632 B

__global__ __launch_bounds__(128, 2) void attn_mma_kernel(
    const float* __restrict__ Q, const float* __restrict__ Kp,
    const float* __restrict__ Vp, int bh_base)
{
    extern __shared__ float sm[];

    const int qb = (int)gridDim.x - 1 - (int)blockIdx.x;   // LPT
    const int bh = bh_base + blockIdx.y;
    const int b = bh >> 4;
    const int h = bh & 15;
    const int tid = threadIdx.x;
    const int w = tid >> 5;
    const int lane = tid & 31;
    const int lm = lane >> 2;
    const int lk = lane & 3;
    const int q0 = qb * 64;

    const float* Qg = Q + ((size_t)bh * T_ + q0) * D_;
    const float* Kg = Kp + (size_t)bh * T_ * D_;
    const float* Vg = Vp + (size_t)bh * T_ * D_;
    const uint32_t smb = smem_u32(sm);

    const int row0g = q0 + w * 16 + lm;
    const int row1g = row0g + 8;

    float qfr[16][4];
    {
        const float* q0p = Qg + (size_t)(w * 16 + lm) * D_;
        const float* q1p = q0p + 8 * D_;
#pragma unroll
        for (int dk = 0; dk < 16; dk++) {
            int col = dk * 8 + lk;
            qfr[dk][0] = to_tf32(q0p[col]);
            qfr[dk][1] = to_tf32(q1p[col]);
            qfr[dk][2] = to_tf32(q0p[col + 4]);
            qfr[dk][3] = to_tf32(q1p[col + 4]);
        }
    }

    float m0 = -1e30f, m1 = -1e30f, l0 = 0.0f, l1 = 0.0f;
    float oacc[16][4];
#pragma unroll
    for (int ni = 0; ni < 16; ni++)
#pragma unroll
        for (int r = 0; r < 4; r++) oacc[ni][r] = 0.0f;

    const float scale = 0.08838834764831845f;
    const int nkv = (q0 + 64) / 32;

    auto load_kv = [&](int kt) {
        const uint32_t dstb = smb + (uint32_t)((kt & 1) * 2 * KV_TILE_F * 4);
        const float* ksrc = Kg + (size_t)kt * 4096;
        const float* vsrc = Vg + (size_t)kt * 4096;
#pragma unroll
        for (int i = 0; i < 8; i++) {
            int c = tid + i * 128;
            int sub = c >> 4, q = c & 15;
            uint32_t off = (uint32_t)((sub * 68 + q * 4) * 4);
            CP_ASYNC16(dstb + off, ksrc + c * 4);
            CP_ASYNC16(dstb + KV_TILE_F * 4 + off, vsrc + c * 4);
        }
        CP_COMMIT();
    };

    load_kv(0);

    for (int kt = 0; kt < nkv; kt++) {
        const int kv0 = kt * 32;
        asm volatile("cp.async.wait_group 0;" ::: "memory");
        __syncthreads();
        if (kt + 1 < nkv) load_kv(kt + 1);

        const float* Ks = sm + (kt & 1) * 2 * KV_TILE_F;
        const float* Vs = Ks + KV_TILE_F;

        float sacc[4][4];
#pragma unroll
        for (int ni = 0; ni < 4; ni++)
#pragma unroll
            for (int r = 0; r < 4; r++) sacc[ni][r] = 0.0f;

#pragma unroll
        for (int dk = 0; dk < 16; dk++) {
#pragma unroll
            for (int ni = 0; ni < 4; ni++) {
                float bfr[2];
                *(float2*)bfr = *(float2*)&Ks[(ni * 16 + dk) * 68 + lane * 2];
                mma_tf32(sacc[ni], qfr[dk], bfr);
            }
        }

        const bool needMask = (kt >= 2 * qb);
#pragma unroll
        for (int ni = 0; ni < 4; ni++) {
            int c0 = kv0 + ni * 8 + 2 * lk;
#pragma unroll
            for (int r = 0; r < 4; r++) sacc[ni][r] *= scale;
            if (needMask) {
                if (c0     > row0g) sacc[ni][0] = -1e30f;
                if (c0 + 1 > row0g) sacc[ni][1] = -1e30f;
                if (c0     > row1g) sacc[ni][2] = -1e30f;
                if (c0 + 1 > row1g) sacc[ni][3] = -1e30f;
            }
        }

        float rmax0 = -1e30f, rmax1 = -1e30f;
#pragma unroll
        for (int ni = 0; ni < 4; ni++) {
            rmax0 = fmaxf(rmax0, fmaxf(sacc[ni][0], sacc[ni][1]));
            rmax1 = fmaxf(rmax1, fmaxf(sacc[ni][2], sacc[ni][3]));
        }
        rmax0 = fmaxf(rmax0, __shfl_xor_sync(0xffffffffu, rmax0, 1));
        rmax0 = fmaxf(rmax0, __shfl_xor_sync(0xffffffffu, rmax0, 2));
        rmax1 = fmaxf(rmax1, __shfl_xor_sync(0xffffffffu, rmax1, 1));
        rmax1 = fmaxf(rmax1, __shfl_xor_sync(0xffffffffu, rmax1, 2));
        float mn0 = fmaxf(m0, rmax0);
        float mn1 = fmaxf(m1, rmax1);
        float al0 = __expf(m0 - mn0);
        float al1 = __expf(m1 - mn1);
        float rs0 = 0.0f, rs1 = 0.0f;
#pragma unroll
        for (int ni = 0; ni < 4; ni++) {
            sacc[ni][0] = __expf(sacc[ni][0] - mn0);
            sacc[ni][1] = __expf(sacc[ni][1] - mn0);
            sacc[ni][2] = __expf(sacc[ni][2] - mn1);
            sacc[ni][3] = __expf(sacc[ni][3] - mn1);
            rs0 += sacc[ni][0] + sacc[ni][1];
            rs1 += sacc[ni][2] + sacc[ni][3];
        }
        rs0 += __shfl_xor_sync(0xffffffffu, rs0, 1);
        rs0 += __shfl_xor_sync(0xffffffffu, rs0, 2);
        rs1 += __shfl_xor_sync(0xffffffffu, rs1, 1);
        rs1 += __shfl_xor_sync(0xffffffffu, rs1, 2);
        l0 = l0 * al0 + rs0;
        l1 = l1 * al1 + rs1;
        m0 = mn0;
        m1 = mn1;
#pragma unroll
        for (int ni = 0; ni < 16; ni++) {
            oacc[ni][0] *= al0; oacc[ni][1] *= al0;
            oacc[ni][2] *= al1; oacc[ni][3] *= al1;
        }

        const int src0 = lm * 4 + (lk >> 1);
        const bool odd = (lk & 1) != 0;
#pragma unroll
        for (int kt2 = 0; kt2 < 4; kt2++) {
            float e00 = __shfl_sync(0xffffffffu, sacc[kt2][0], src0);
            float e10 = __shfl_sync(0xffffffffu, sacc[kt2][1], src0);
            float e20 = __shfl_sync(0xffffffffu, sacc[kt2][2], src0);
            float e30 = __shfl_sync(0xffffffffu, sacc[kt2][3], src0);
            float e01 = __shfl_sync(0xffffffffu, sacc[kt2][0], src0 + 2);
            float e11 = __shfl_sync(0xffffffffu, sacc[kt2][1], src0 + 2);
            float e21 = __shfl_sync(0xffffffffu, sacc[kt2][2], src0 + 2);
            float e31 = __shfl_sync(0xffffffffu, sacc[kt2][3], src0 + 2);
            float afr[4];
            afr[0] = to_tf32(odd ? e10 : e00);
            afr[1] = to_tf32(odd ? e30 : e20);
            afr[2] = to_tf32(odd ? e11 : e01);
            afr[3] = to_tf32(odd ? e31 : e21);
#pragma unroll
            for (int ni = 0; ni < 16; ni++) {
                float bfr[2];
                *(float2*)bfr = *(float2*)&Vs[(kt2 * 16 + ni) * 68 + lane * 2];
                mma_tf32(oacc[ni], afr, bfr);
            }
        }
    }

    float inv0 = 1.0f / l0;
    float inv1 = 1.0f / l1;
    const size_t rowg = (size_t)b * T_ + (size_t)row0g;
    const size_t pglob = (rowg >> 4) * 8 + (rowg & 7);
#pragma unroll
    for (int ni = 0; ni < 16; ni++) {
        int col = h * D_ + ni * 8 + 2 * lk;
        float4 v;
        v.x = to_tf32(oacc[ni][0] * inv0);
        v.y = to_tf32(oacc[ni][2] * inv1);
        v.z = to_tf32(oacc[ni][1] * inv0);
        v.w = to_tf32(oacc[ni][3] * inv1);
        *(float4*)&g_attn[(pglob * C_ + col) * 2] = v;
    }
}

// ---------------- launch: 3-stream packs + split-batch dual pipeline ------------
extern "C" void kernel_launch(void* const* d_in, const int* in_sizes, int n_in,
                              void* d_out, int out_size)
{
    const float* x      = (const float*)d_in[0];
    const float* cosg   = (const float*)d_in[1];
    const float* sing   = (const float*)d_in[2];
    const float* W_qkv  = (const float*)d_in[3];
    const float* W_proj = (const float*)d_in[4];
    float* out = (float*)d_out;

    float* Qb;     cudaGetSymbolAddress((void**)&Qb,     g_Q);
    float* Kb;     cudaGetSymbolAddress((void**)&Kb,     g_K);
    float* Vb;     cudaGetSymbolAddress((void**)&Vb,     g_V);
    float* attn;   cudaGetSymbolAddress((void**)&attn,   g_attn);
    float* xc;     cudaGetSymbolAddress((void**)&xc,     g_xc);
    float* wqkvC;  cudaGetSymbolAddress((void**)&wqkvC,  g_wqkvC);
    float* wprojC; cudaGetSymbolAddress((void**)&wprojC, g_wprojC);

    const int M = B_ * T_;   // 4096

    static cudaStream_t s2 = nullptr, s3 = nullptr;
    static cudaEvent_t evA = nullptr, evB = nullptr, evP = nullptr, evJ = nullptr;
    if (s2 == nullptr) {
        cudaStreamCreateWithFlags(&s2, cudaStreamNonBlocking);
        cudaStreamCreateWithFlags(&s3, cudaStreamNonBlocking);
        cudaEventCreateWithFlags(&evA, cudaEventDisableTiming);
        cudaEventCreateWithFlags(&evB, cudaEventDisableTiming);
        cudaEventCreateWithFlags(&evP, cudaEventDisableTiming);
        cudaEventCreateWithFlags(&evJ, cudaEventDisableTiming);
    }

    cudaFuncSetAttribute(gemm_v6_kernel,
                         cudaFuncAttributeMaxDynamicSharedMemorySize, V5_SMEM_BYTES);
    cudaFuncSetAttribute(attn_mma_kernel,
                         cudaFuncAttributeMaxDynamicSharedMemorySize,
                         ATTN_SMEM_FLOATS * sizeof(float));

    // fork s2/s3 off stream 0 first (so capture sees a proper fork)
    cudaEventRecord(evJ, 0);                 // reuse evJ as the fork marker
    cudaStreamWaitEvent(s2, evJ, 0);
    cudaStreamWaitEvent(s3, evJ, 0);

    // packs in parallel: A on stream0, B_qkv on s2, B_proj on s3
    {
        int na = (M * C_) / 4;
        pack_a_kernel<<<(na + 255) / 256, 256>>>(x, xc, C_, na);
        cudaEventRecord(evA, 0);
        int nbq = (C_ * 3 * C_) / 4;
        pack_b_kernel<<<(nbq + 255) / 256, 256, 0, s2>>>(W_qkv, wqkvC, 3 * C_, nbq);
        cudaEventRecord(evB, s2);
        int nbp = (C_ * C_) / 4;
        pack_b_kernel<<<(nbp + 255) / 256, 256, 0, s3>>>(W_proj, wprojC, C_, nbp);
        cudaEventRecord(evP, s3);
    }

    // cross-deps: qkv(b0) on stream0 needs evB; qkv(b1) on s2 needs evA
    cudaStreamWaitEvent(0, evB, 0);
    cudaStreamWaitEvent(s2, evA, 0);

    const dim3 gQKV(3 * C_ / V5_BN, 16);   // per-batch: (48, 16)
    const dim3 gATT(T_ / 64, 16);          // per-batch: (32, 16)
    const dim3 gPRJ(C_ / V5_BN, 16);       // per-batch: (16, 16)
    const size_t aSm = ATTN_SMEM_FLOATS * sizeof(float);

    // batch 0 on main stream
    gemm_v6_kernel<<<gQKV, 256, V5_SMEM_BYTES>>>(
        xc, wqkvC, nullptr, cosg, sing, Qb, Kb, Vb, M, 3 * C_, C_, 1, 0);
    attn_mma_kernel<<<gATT, 128, aSm>>>(Qb, Kb, Vb, 0);
    cudaStreamWaitEvent(0, evP, 0);
    gemm_v6_kernel<<<gPRJ, 256, V5_SMEM_BYTES>>>(
        attn, wprojC, out, nullptr, nullptr, nullptr, nullptr, nullptr,
        M, C_, C_, 0, 0);

    // batch 1 on s2
    gemm_v6_kernel<<<gQKV, 256, V5_SMEM_BYTES, s2>>>(
        xc, wqkvC, nullptr, cosg, sing, Qb, Kb, Vb, M, 3 * C_, C_, 1, 2048);
    attn_mma_kernel<<<gATT, 128, aSm, s2>>>(Qb, Kb, Vb, 16);
    cudaStreamWaitEvent(s2, evP, 0);
    gemm_v6_kernel<<<gPRJ, 256, V5_SMEM_BYTES, s2>>>(
        attn, wprojC, out, nullptr, nullptr, nullptr, nullptr, nullptr,
        M, C_, C_, 0, 2048);

    // join s2 back into stream 0
    cudaEventRecord(evB, s2);   // reuse evB as join marker (safe: prior use consumed)
    cudaStreamWaitEvent(0, evB, 0);
}